// round 6
// baseline (speedup 1.0000x reference)
#include <cuda_runtime.h>
#include <cuda_fp16.h>
#include <math.h>

#define NMAX 50000
#define EMAX 1600000
#define FIN 16
#define TT 12
#define HID 32
#define FT (FIN*TT)   // 192 values per node
#define SCB 512       // scan block size

// ---------------- scratch (static device globals; no allocation) ----------------
__device__ int    g_cnt[NMAX];                    // in-degree counts (excl. self-loop)
__device__ int    g_rowptr[NMAX + 1];             // CSR row pointers
__device__ int    g_cur[NMAX];                    // fill cursors
__device__ int2   g_sw[EMAX];                     // CSR payload: {src, bits(norm weight)}
__device__ int    g_pref[256];                    // chained-scan inclusive prefixes
__device__ int    g_flag[256];                    // chained-scan ready flags
__device__ float  g_dis[NMAX];                    // rsqrt(degree incl. self-loop)
__device__ __half g_xh[(size_t)NMAX * FT];        // fp16 features, t-major [N][T][F]
__device__ float  g_agg[(size_t)NMAX * FT];       // aggregated features, t-major [N][T][F]
__device__ float  g_A[3 * FIN * HID];             // folded W_g @ L_g_top
__device__ float  g_c[3 * HID];                   // folded biases
__device__ float  g_probs[TT];                    // softmax(att)
__device__ float  g_hsum[HID];                    // sum over nodes of relu(Hacc)
__device__ int    g_done;                         // gru completion counter

// ---------------- helpers ----------------
__device__ __forceinline__ float sigf(float x) {
    return __fdividef(1.0f, 1.0f + __expf(-x));
}
__device__ __forceinline__ float tanhfast(float x) {
    return fmaf(2.0f, __fdividef(1.0f, 1.0f + __expf(-2.0f * x)), -1.0f);
}

// packed f32x2 helpers (Blackwell FFMA2)
typedef unsigned long long u64;
__device__ __forceinline__ u64 pk2(float x, float y) {
    u64 r; asm("mov.b64 %0, {%1,%2};" : "=l"(r) : "f"(x), "f"(y)); return r;
}
__device__ __forceinline__ u64 fma2(u64 a, u64 b, u64 c) {
    u64 d; asm("fma.rn.f32x2 %0, %1, %2, %3;" : "=l"(d) : "l"(a), "l"(b), "l"(c)); return d;
}
__device__ __forceinline__ void up2(u64 v, float& x, float& y) {
    asm("mov.b64 {%0,%1}, %2;" : "=f"(x), "=f"(y) : "l"(v));
}
union F4U2 { float4 f4; u64 u[2]; };
union F4H2 { float4 f4; __half2 h2[4]; };

// =======================================================================
// 1) k_pre: fp16 transpose of x, edge-count atomics, weight fold + softmax
//    grid = (N+3)/4 blocks of 256 (3.2M threads >= E)
// =======================================================================
__global__ void __launch_bounds__(256)
k_pre(const float* __restrict__ x, const int* __restrict__ ei,
      const float* __restrict__ Wz, const float* __restrict__ bz,
      const float* __restrict__ Wr, const float* __restrict__ br,
      const float* __restrict__ Wh, const float* __restrict__ bh,
      const float* __restrict__ LzW, const float* __restrict__ Lzb,
      const float* __restrict__ LrW, const float* __restrict__ Lrb,
      const float* __restrict__ LhW, const float* __restrict__ Lhb,
      const float* __restrict__ att, int N, int E) {
    __shared__ float sx[4 * FT];
    int tid = threadIdx.x;

    // --- edge count atomics (first E global threads) ---
    int gt = blockIdx.x * 256 + tid;
    if (gt < E) atomicAdd(&g_cnt[ei[E + gt]], 1);

    // --- conversion: 4 nodes per block, [N][F][T] f32 -> [N][T][F] f16 ---
    size_t base = (size_t)blockIdx.x * 4 * FT;
    size_t lim  = (size_t)N * FT;
    #pragma unroll
    for (int i = tid; i < 4 * FT; i += 256) {
        size_t g = base + i;
        if (g < lim) sx[i] = x[g];
    }
    __syncthreads();
    #pragma unroll
    for (int i = tid; i < 4 * FT; i += 256) {
        size_t g = base + i;
        if (g < lim) {
            int nn = i / FT, p = i % FT;
            int t = p / FIN, f = p % FIN;
            g_xh[g] = __float2half(sx[nn * FT + f * TT + t]);
        }
    }

    // --- weight folding + softmax (block 0 only) ---
    if (blockIdx.x == 0) {
        const float* W[3]  = {Wz, Wr, Wh};
        const float* L[3]  = {LzW, LrW, LhW};
        const float* bb[3] = {bz, br, bh};
        const float* Lb[3] = {Lzb, Lrb, Lhb};
        #pragma unroll
        for (int rep = 0; rep < 2; rep++) {
            int id = tid + rep * 256;            // 512 (f,j) pairs
            int f = id >> 5, j = id & 31;
            #pragma unroll
            for (int g = 0; g < 3; g++) {
                float s = 0.0f;
                #pragma unroll
                for (int k = 0; k < HID; k++)
                    s = fmaf(__ldg(&W[g][f * HID + k]), __ldg(&L[g][k * HID + j]), s);
                g_A[(g * FIN + f) * HID + j] = s;
            }
        }
        if (tid < 3 * HID) {
            int g = tid >> 5, jj = tid & 31;
            float s = __ldg(&Lb[g][jj]);
            #pragma unroll
            for (int k = 0; k < HID; k++)
                s = fmaf(__ldg(&bb[g][k]), __ldg(&L[g][k * HID + jj]), s);
            g_c[g * HID + jj] = s;
        }
        if (tid < 32) {
            float v = (tid < TT) ? __ldg(&att[tid]) : -1e30f;
            float m = v;
            #pragma unroll
            for (int o = 16; o; o >>= 1) m = fmaxf(m, __shfl_xor_sync(0xffffffffu, m, o));
            float e = (tid < TT) ? __expf(v - m) : 0.0f;
            float s = e;
            #pragma unroll
            for (int o = 16; o; o >>= 1) s += __shfl_xor_sync(0xffffffffu, s, o);
            if (tid < TT) g_probs[tid] = e * __fdividef(1.0f, s);
        }
    }
}

// =======================================================================
// 2) k_scan: single-pass chained block scan (98 blocks, all co-resident)
//    also writes rowptr / cur / dis
// =======================================================================
__global__ void __launch_bounds__(SCB)
k_scan(int N, int E, int NB) {
    __shared__ int ws[SCB / 32];
    __shared__ int sbase;
    int tid = threadIdx.x, lane = tid & 31, wid = tid >> 5;
    int b = blockIdx.x;
    int i = b * SCB + tid;
    int c = (i < N) ? g_cnt[i] : 0;

    // block-wide inclusive scan
    int v = c;
    #pragma unroll
    for (int o = 1; o < 32; o <<= 1) {
        int t = __shfl_up_sync(0xffffffffu, v, o);
        if (lane >= o) v += t;
    }
    if (lane == 31) ws[wid] = v;
    __syncthreads();
    if (wid == 0 && lane < SCB / 32) {
        int w = ws[lane];
        #pragma unroll
        for (int o = 1; o < SCB / 32; o <<= 1) {
            int t = __shfl_up_sync(0xffffu, w, o);
            if (lane >= o) w += t;
        }
        ws[lane] = w;
    }
    __syncthreads();
    int incl = v + (wid > 0 ? ws[wid - 1] : 0);
    int btotal = ws[SCB / 32 - 1];

    // chain: wait for left neighbor's inclusive prefix
    if (tid == 0) {
        int base = 0;
        if (b > 0) {
            while (((volatile int*)g_flag)[b - 1] == 0) { }
            __threadfence();
            base = ((volatile int*)g_pref)[b - 1];
        }
        sbase = base;
        ((volatile int*)g_pref)[b] = base + btotal;
        __threadfence();
        ((volatile int*)g_flag)[b] = 1;
    }
    __syncthreads();

    int excl = sbase + incl - c;
    if (i < N) {
        g_rowptr[i] = excl;
        g_cur[i]    = excl;
        g_dis[i]    = rsqrtf((float)(c + 1));    // +1 self-loop
    }
    if (b == NB - 1 && tid == 0) g_rowptr[N] = E;
}

// =======================================================================
// 3) k_fill: CSR fill + cleanup of g_cnt / g_flag for next replay
// =======================================================================
__global__ void k_fill(const int* __restrict__ ei, int E, int N, int NB) {
    int e = blockIdx.x * blockDim.x + threadIdx.x;
    if (e < N) g_cnt[e] = 0;            // cnt is dead after k_scan
    if (e < NB) g_flag[e] = 0;          // scan flags dead too
    if (e >= E) return;
    int s = ei[e];
    int d = ei[E + e];
    int p = atomicAdd(&g_cur[d], 1);
    g_sw[p] = make_int2(s, __float_as_int(g_dis[s] * g_dis[d]));
}

// =======================================================================
// 4) k_gather: warp-per-node gather on fp16 features (fp32 accumulation)
// =======================================================================
__global__ void __launch_bounds__(256)
k_gather(int N) {
    __shared__ int2 stage[8][32];
    int gw   = (blockIdx.x * blockDim.x + threadIdx.x) >> 5;
    int wloc = threadIdx.x >> 5;
    int lane = threadIdx.x & 31;
    if (gw >= N) return;
    int n = gw;

    int beg = g_rowptr[n];
    int end = g_rowptr[n + 1];
    float dd = g_dis[n];
    int ln = (lane < 24) ? lane : 0;        // clamped payload lane

    float acc[8];
    {
        float inv = dd * dd;                       // 1/deg (self-loop term)
        F4H2 v; v.f4 = ((const float4*)(g_xh + (size_t)n * FT))[ln];
        #pragma unroll
        for (int q = 0; q < 4; q++) {
            float2 f = __half22float2(v.h2[q]);
            acc[2 * q]     = inv * f.x;
            acc[2 * q + 1] = inv * f.y;
        }
    }

    for (int i = beg; i < end; i += 32) {
        int j = i + lane;
        if (j < end) stage[wloc][lane] = g_sw[j];
        __syncwarp();
        int m = min(32, end - i);
        #pragma unroll 8
        for (int u = 0; u < m; u++) {
            int2 sw = stage[wloc][u];
            float ww = __int_as_float(sw.y);
            F4H2 v; v.f4 = ((const float4*)(g_xh + (size_t)sw.x * FT))[ln];
            #pragma unroll
            for (int q = 0; q < 4; q++) {
                float2 f = __half22float2(v.h2[q]);
                acc[2 * q]     = fmaf(ww, f.x, acc[2 * q]);
                acc[2 * q + 1] = fmaf(ww, f.y, acc[2 * q + 1]);
            }
        }
        __syncwarp();
    }

    if (lane < 24) {
        float4* ap = (float4*)(g_agg + (size_t)n * FT);
        ap[2 * lane]     = make_float4(acc[0], acc[1], acc[2], acc[3]);
        ap[2 * lane + 1] = make_float4(acc[4], acc[5], acc[6], acc[7]);
    }
}

// One gate pre-activation: out2[16] (packed pairs) =
//   cvec + sum_f apk[f]*A[f] + sum_k Hv[k]*B[k]
__device__ __forceinline__ void gate_accum(
    u64* out2,
    const float4 (*A)[HID / 4], const float4 (*B)[HID / 4],
    const float4* cvec, const u64* apk, const float* Hv)
{
    #pragma unroll
    for (int j4 = 0; j4 < HID / 4; j4++) {
        F4U2 c; c.f4 = cvec[j4];
        out2[2 * j4] = c.u[0]; out2[2 * j4 + 1] = c.u[1];
    }
    #pragma unroll 4
    for (int f = 0; f < FIN; f++) {
        u64 av = apk[f];
        #pragma unroll
        for (int j4 = 0; j4 < HID / 4; j4++) {
            F4U2 w; w.f4 = A[f][j4];
            out2[2 * j4]     = fma2(av, w.u[0], out2[2 * j4]);
            out2[2 * j4 + 1] = fma2(av, w.u[1], out2[2 * j4 + 1]);
        }
    }
    #pragma unroll 4
    for (int k = 0; k < HID; k++) {
        u64 hk = pk2(Hv[k], Hv[k]);
        #pragma unroll
        for (int j4 = 0; j4 < HID / 4; j4++) {
            F4U2 w; w.f4 = B[k][j4];
            out2[2 * j4]     = fma2(hk, w.u[0], out2[2 * j4]);
            out2[2 * j4 + 1] = fma2(hk, w.u[1], out2[2 * j4 + 1]);
        }
    }
}

// =======================================================================
// 5) k_gru: per-node GRU over T=12 steps + fused final readout
// =======================================================================
__global__ void __launch_bounds__(128, 2)
k_gru(const float* __restrict__ LzW, const float* __restrict__ LrW,
      const float* __restrict__ LhW, const float* __restrict__ linW,
      const float* __restrict__ linb, float* __restrict__ out, int N) {
    __shared__ float4 sA[3][FIN][HID / 4];   // folded A matrices
    __shared__ float4 sB[3][HID][HID / 4];   // bottom halves of L matrices
    __shared__ float4 sc[3][HID / 4];        // folded biases
    __shared__ float  sp[TT];
    __shared__ float  bsum[HID];
    __shared__ int    islast;

    int tid = threadIdx.x;
    {
        float* pA = (float*)sA;
        for (int i = tid; i < 3 * FIN * HID; i += 128) pA[i] = g_A[i];
        float* pB = (float*)sB;
        for (int i = tid; i < HID * HID; i += 128) {
            pB[i]                 = LzW[HID * HID + i];
            pB[HID * HID + i]     = LrW[HID * HID + i];
            pB[2 * HID * HID + i] = LhW[HID * HID + i];
        }
        float* pc = (float*)sc;
        if (tid < 3 * HID) pc[tid] = g_c[tid];
        if (tid < TT) sp[tid] = g_probs[tid];
        if (tid < HID) bsum[tid] = 0.0f;
    }
    __syncthreads();

    int n = blockIdx.x * 128 + tid;
    if (n < N) {
        float H[HID], acc[HID];
        #pragma unroll
        for (int j = 0; j < HID; j++) { H[j] = 0.0f; acc[j] = 0.0f; }
        const float4* ap4 = (const float4*)(g_agg + (size_t)n * FT);

        #pragma unroll 1
        for (int t = 0; t < TT; t++) {
            u64 apk[FIN];
            {
                float4 a0 = __ldg(&ap4[4 * t + 0]);
                float4 a1 = __ldg(&ap4[4 * t + 1]);
                float4 a2 = __ldg(&ap4[4 * t + 2]);
                float4 a3 = __ldg(&ap4[4 * t + 3]);
                apk[0]  = pk2(a0.x, a0.x); apk[1]  = pk2(a0.y, a0.y);
                apk[2]  = pk2(a0.z, a0.z); apk[3]  = pk2(a0.w, a0.w);
                apk[4]  = pk2(a1.x, a1.x); apk[5]  = pk2(a1.y, a1.y);
                apk[6]  = pk2(a1.z, a1.z); apk[7]  = pk2(a1.w, a1.w);
                apk[8]  = pk2(a2.x, a2.x); apk[9]  = pk2(a2.y, a2.y);
                apk[10] = pk2(a2.z, a2.z); apk[11] = pk2(a2.w, a2.w);
                apk[12] = pk2(a3.x, a3.x); apk[13] = pk2(a3.y, a3.y);
                apk[14] = pk2(a3.z, a3.z); apk[15] = pk2(a3.w, a3.w);
            }
            float p = sp[t];
            u64 t2[HID / 2];

            // ---- z gate ----
            float Z[HID];
            gate_accum(t2, sA[0], sB[0], sc[0], apk, H);
            #pragma unroll
            for (int j2 = 0; j2 < HID / 2; j2++) {
                float x0, x1;
                up2(t2[j2], x0, x1);
                Z[2 * j2] = sigf(x0); Z[2 * j2 + 1] = sigf(x1);
            }

            // ---- r gate (folded with H) ----
            float R[HID];
            gate_accum(t2, sA[1], sB[1], sc[1], apk, H);
            #pragma unroll
            for (int j2 = 0; j2 < HID / 2; j2++) {
                float x0, x1;
                up2(t2[j2], x0, x1);
                R[2 * j2]     = sigf(x0) * H[2 * j2];
                R[2 * j2 + 1] = sigf(x1) * H[2 * j2 + 1];
            }

            // ---- candidate h + state update ----
            gate_accum(t2, sA[2], sB[2], sc[2], apk, R);
            #pragma unroll
            for (int j2 = 0; j2 < HID / 2; j2++) {
                float h0, h1;
                up2(t2[j2], h0, h1);
                int j = 2 * j2;
                {
                    float ht = tanhfast(h0); float zt = Z[j];
                    H[j] = zt * H[j] + (1.0f - zt) * ht;
                    acc[j] = fmaf(p, H[j], acc[j]);
                }
                {
                    float ht = tanhfast(h1); float zt = Z[j + 1];
                    H[j + 1] = zt * H[j + 1] + (1.0f - zt) * ht;
                    acc[j + 1] = fmaf(p, H[j + 1], acc[j + 1]);
                }
            }
        }
        #pragma unroll
        for (int j = 0; j < HID; j++) {
            float v = acc[j] > 0.0f ? acc[j] : 0.0f;
            atomicAdd(&bsum[j], v);
        }
    }
    __syncthreads();
    if (tid < HID) atomicAdd(&g_hsum[tid], bsum[tid]);

    // ---- fused final readout: last block to finish reduces g_hsum ----
    if (tid == 0) {
        __threadfence();
        int d = atomicAdd(&g_done, 1);
        islast = (d == (int)gridDim.x - 1) ? 1 : 0;
    }
    __syncthreads();
    if (islast) {
        if (tid < 32) {
            float v = atomicAdd(&g_hsum[tid], 0.0f);     // coherent read
            float invN = 1.0f / (float)N;
            float s = v * invN * __ldg(&linW[tid]);
            #pragma unroll
            for (int o = 16; o; o >>= 1) s += __shfl_xor_sync(0xffffffffu, s, o);
            if (tid == 0) {
                float r = s + __ldg(&linb[0]);
                out[0] = r > 0.0f ? r : 0.0f;
                g_done = 0;                              // reset for next replay
            }
            g_hsum[tid] = 0.0f;                          // reset for next replay
        }
    }
}

// ---------------- launcher ----------------
extern "C" void kernel_launch(void* const* d_in, const int* in_sizes, int n_in,
                              void* d_out, int out_size) {
    const float* x    = (const float*)d_in[0];
    const int*   ei   = (const int*)  d_in[1];
    const float* att  = (const float*)d_in[2];
    const float* Wz   = (const float*)d_in[3];
    const float* bz   = (const float*)d_in[4];
    const float* Wr   = (const float*)d_in[5];
    const float* br   = (const float*)d_in[6];
    const float* Wh   = (const float*)d_in[7];
    const float* bh   = (const float*)d_in[8];
    const float* LzW  = (const float*)d_in[9];
    const float* Lzb  = (const float*)d_in[10];
    const float* LrW  = (const float*)d_in[11];
    const float* Lrb  = (const float*)d_in[12];
    const float* LhW  = (const float*)d_in[13];
    const float* Lhb  = (const float*)d_in[14];
    const float* linW = (const float*)d_in[15];
    const float* linb = (const float*)d_in[16];

    int N = in_sizes[0] / FT;
    int E = in_sizes[1] / 2;
    int NB = (N + SCB - 1) / SCB;

    k_pre<<<(N + 3) / 4, 256>>>(x, ei, Wz, bz, Wr, br, Wh, bh,
                                LzW, Lzb, LrW, Lrb, LhW, Lhb, att, N, E);
    k_scan<<<NB, SCB>>>(N, E, NB);
    k_fill<<<(E + 255) / 256, 256>>>(ei, E, N, NB);
    k_gather<<<(N * 32 + 255) / 256, 256>>>(N);
    k_gru<<<(N + 127) / 128, 128>>>(LzW, LrW, LhW, linW, linb, (float*)d_out, N);
}

// round 7
// speedup vs baseline: 1.2010x; 1.2010x over previous
#include <cuda_runtime.h>
#include <cuda_fp16.h>
#include <math.h>

#define NMAX 50000
#define EMAX 1600000
#define FIN 16
#define TT 12
#define HID 32
#define FT (FIN*TT)   // 192 values per node
#define SB 512        // scan block size

// ---------------- scratch (static device globals; no allocation) ----------------
__device__ int    g_cnt[NMAX];                    // in-degree counts (excl. self-loop)
__device__ int    g_rowptr[NMAX + 1];             // CSR row pointers
__device__ int    g_cur[NMAX];                    // fill cursors
__device__ int2   g_sw[EMAX];                     // CSR payload: {src, bits(norm weight)}
__device__ int    g_part[256];                    // scan partials
__device__ float  g_dis[NMAX];                    // rsqrt(degree incl. self-loop)
__device__ __half g_xh[(size_t)NMAX * FT];        // fp16 features, t-major [N][T][F]
__device__ float  g_agg[(size_t)NMAX * FT];       // aggregated features, t-major [N][T][F]
__device__ float  g_A[3 * FIN * HID];             // folded W_g @ L_g_top
__device__ float  g_c[3 * HID];                   // folded biases
__device__ float  g_probs[TT];                    // softmax(att)
__device__ float  g_hsum[HID];                    // sum over nodes of relu(Hacc)

// ---------------- helpers ----------------
__device__ __forceinline__ float sigf(float x) {
    return __fdividef(1.0f, 1.0f + __expf(-x));
}
__device__ __forceinline__ float tanhfast(float x) {
    return fmaf(2.0f, __fdividef(1.0f, 1.0f + __expf(-2.0f * x)), -1.0f);
}

// packed f32x2 helpers (Blackwell FFMA2)
typedef unsigned long long u64;
__device__ __forceinline__ u64 pk2(float x, float y) {
    u64 r; asm("mov.b64 %0, {%1,%2};" : "=l"(r) : "f"(x), "f"(y)); return r;
}
__device__ __forceinline__ u64 fma2(u64 a, u64 b, u64 c) {
    u64 d; asm("fma.rn.f32x2 %0, %1, %2, %3;" : "=l"(d) : "l"(a), "l"(b), "l"(c)); return d;
}
__device__ __forceinline__ void up2(u64 v, float& x, float& y) {
    asm("mov.b64 {%0,%1}, %2;" : "=f"(x), "=f"(y) : "l"(v));
}
union F4U2 { float4 f4; u64 u[2]; };
union F4H2 { float4 f4; __half2 h2[4]; };

// ---------------- kernels ----------------
__global__ void k_zero(int N) {
    int i = blockIdx.x * blockDim.x + threadIdx.x;
    if (i < N) g_cnt[i] = 0;
    if (i < HID) g_hsum[i] = 0.0f;
}

__global__ void k_cnt(const int* __restrict__ ei, int E) {
    int e = blockIdx.x * blockDim.x + threadIdx.x;
    if (e < E) atomicAdd(&g_cnt[ei[E + e]], 1);
}

// Convert x [N][F][T] fp32 -> g_xh [N][T][F] fp16. 4 nodes per block of 256.
__global__ void k_half(const float* __restrict__ x, int N) {
    __shared__ float sx[4 * FT];
    int tid = threadIdx.x;
    size_t base = (size_t)blockIdx.x * 4 * FT;
    size_t lim  = (size_t)N * FT;
    #pragma unroll
    for (int i = tid; i < 4 * FT; i += 256) {
        size_t g = base + i;
        if (g < lim) sx[i] = x[g];
    }
    __syncthreads();
    #pragma unroll
    for (int i = tid; i < 4 * FT; i += 256) {
        size_t g = base + i;
        if (g < lim) {
            int nn = i / FT, p = i % FT;
            int t = p / FIN, f = p % FIN;
            g_xh[g] = __float2half(sx[nn * FT + f * TT + t]);
        }
    }
}

// Precompute folded matrices A_g = W_g @ L_g[0:32,:], c_g = b_g @ L_g[0:32,:] + Lgb,
// and softmax(att). One block of 512 threads.
__global__ void k_prep(const float* __restrict__ Wz, const float* __restrict__ bz,
                       const float* __restrict__ Wr, const float* __restrict__ br,
                       const float* __restrict__ Wh, const float* __restrict__ bh,
                       const float* __restrict__ LzW, const float* __restrict__ Lzb,
                       const float* __restrict__ LrW, const float* __restrict__ Lrb,
                       const float* __restrict__ LhW, const float* __restrict__ Lhb,
                       const float* __restrict__ att) {
    int id = threadIdx.x;                       // 512 threads
    const float* W[3]  = {Wz, Wr, Wh};
    const float* L[3]  = {LzW, LrW, LhW};
    const float* bb[3] = {bz, br, bh};
    const float* Lb[3] = {Lzb, Lrb, Lhb};

    int f = id >> 5, j = id & 31;               // 16 x 32 = 512
    #pragma unroll
    for (int g = 0; g < 3; g++) {
        float s = 0.0f;
        #pragma unroll
        for (int k = 0; k < HID; k++)
            s = fmaf(__ldg(&W[g][f * HID + k]), __ldg(&L[g][k * HID + j]), s);
        g_A[(g * FIN + f) * HID + j] = s;
    }
    if (id < 3 * HID) {
        int g = id >> 5, jj = id & 31;
        float s = __ldg(&Lb[g][jj]);
        #pragma unroll
        for (int k = 0; k < HID; k++)
            s = fmaf(__ldg(&bb[g][k]), __ldg(&L[g][k * HID + jj]), s);
        g_c[g * HID + jj] = s;
    }
    if (id < 32) {
        float v = (id < TT) ? __ldg(&att[id]) : -1e30f;
        float m = v;
        #pragma unroll
        for (int o = 16; o; o >>= 1) m = fmaxf(m, __shfl_xor_sync(0xffffffffu, m, o));
        float e = (id < TT) ? __expf(v - m) : 0.0f;
        float s = e;
        #pragma unroll
        for (int o = 16; o; o >>= 1) s += __shfl_xor_sync(0xffffffffu, s, o);
        if (id < TT) g_probs[id] = e * __fdividef(1.0f, s);
    }
}

// ---- parallel 3-phase scan ----
__global__ void k_scan_a(int N) {
    __shared__ int ws[SB / 32];
    int tid = threadIdx.x;
    int i = blockIdx.x * SB + tid;
    int v = (i < N) ? g_cnt[i] : 0;
    #pragma unroll
    for (int o = 16; o; o >>= 1) v += __shfl_xor_sync(0xffffffffu, v, o);
    if ((tid & 31) == 0) ws[tid >> 5] = v;
    __syncthreads();
    if (tid < SB / 32) {
        int w = ws[tid];
        #pragma unroll
        for (int o = 8; o; o >>= 1) w += __shfl_xor_sync(0xffffu, w, o);
        if (tid == 0) g_part[blockIdx.x] = w;
    }
}

__global__ void k_scan_b(int NB, int N, int E) {
    __shared__ int ws[4];
    int tid = threadIdx.x, lane = tid & 31, wid = tid >> 5;
    int orig = (tid < NB) ? g_part[tid] : 0;
    int v = orig;
    #pragma unroll
    for (int o = 1; o < 32; o <<= 1) {
        int t = __shfl_up_sync(0xffffffffu, v, o);
        if (lane >= o) v += t;
    }
    if (lane == 31) ws[wid] = v;
    __syncthreads();
    if (wid == 0 && lane < 4) {
        int w = ws[lane];
        #pragma unroll
        for (int o = 1; o < 4; o <<= 1) {
            int t = __shfl_up_sync(0xfu, w, o);
            if (lane >= o) w += t;
        }
        ws[lane] = w;
    }
    __syncthreads();
    int incl = v + (wid > 0 ? ws[wid - 1] : 0);
    if (tid < NB) g_part[tid] = incl - orig;     // exclusive
    if (tid == 0) g_rowptr[N] = E;
}

__global__ void k_scan_c(int N) {
    __shared__ int ws[SB / 32];
    int tid = threadIdx.x, lane = tid & 31, wid = tid >> 5;
    int i = blockIdx.x * SB + tid;
    int c = (i < N) ? g_cnt[i] : 0;
    int v = c;
    #pragma unroll
    for (int o = 1; o < 32; o <<= 1) {
        int t = __shfl_up_sync(0xffffffffu, v, o);
        if (lane >= o) v += t;
    }
    if (lane == 31) ws[wid] = v;
    __syncthreads();
    if (wid == 0 && lane < SB / 32) {
        int w = ws[lane];
        #pragma unroll
        for (int o = 1; o < SB / 32; o <<= 1) {
            int t = __shfl_up_sync((1u << (SB / 32)) - 1u, w, o);
            if (lane >= o) w += t;
        }
        ws[lane] = w;
    }
    __syncthreads();
    int excl = v - c + (wid > 0 ? ws[wid - 1] : 0) + g_part[blockIdx.x];
    if (i < N) {
        g_rowptr[i] = excl;
        g_cur[i]    = excl;
        g_dis[i]    = rsqrtf((float)(c + 1));    // +1 self-loop
    }
}

// CSR fill with folded norm weight: payload {src, dis[s]*dis[d]}
__global__ void k_fill(const int* __restrict__ ei, int E) {
    int e = blockIdx.x * blockDim.x + threadIdx.x;
    if (e >= E) return;
    int s = ei[e];
    int d = ei[E + e];
    int p = atomicAdd(&g_cur[d], 1);
    g_sw[p] = make_int2(s, __float_as_int(g_dis[s] * g_dis[d]));
}

// Warp-per-node gather on fp16 features (fp32 accumulation).
__global__ void __launch_bounds__(256)
k_gather(int N) {
    __shared__ int2 stage[8][32];
    int gw   = (blockIdx.x * blockDim.x + threadIdx.x) >> 5;
    int wloc = threadIdx.x >> 5;
    int lane = threadIdx.x & 31;
    if (gw >= N) return;
    int n = gw;

    int beg = g_rowptr[n];
    int end = g_rowptr[n + 1];
    float dd = g_dis[n];
    int ln = (lane < 24) ? lane : 0;        // clamped payload lane

    float acc[8];
    {
        float inv = dd * dd;                       // 1/deg (self-loop term)
        F4H2 v; v.f4 = ((const float4*)(g_xh + (size_t)n * FT))[ln];
        #pragma unroll
        for (int q = 0; q < 4; q++) {
            float2 f = __half22float2(v.h2[q]);
            acc[2 * q]     = inv * f.x;
            acc[2 * q + 1] = inv * f.y;
        }
    }

    for (int i = beg; i < end; i += 32) {
        int j = i + lane;
        if (j < end) stage[wloc][lane] = g_sw[j];
        __syncwarp();
        int m = min(32, end - i);
        #pragma unroll 8
        for (int u = 0; u < m; u++) {
            int2 sw = stage[wloc][u];
            float ww = __int_as_float(sw.y);
            F4H2 v; v.f4 = ((const float4*)(g_xh + (size_t)sw.x * FT))[ln];
            #pragma unroll
            for (int q = 0; q < 4; q++) {
                float2 f = __half22float2(v.h2[q]);
                acc[2 * q]     = fmaf(ww, f.x, acc[2 * q]);
                acc[2 * q + 1] = fmaf(ww, f.y, acc[2 * q + 1]);
            }
        }
        __syncwarp();
    }

    if (lane < 24) {
        float4* ap = (float4*)(g_agg + (size_t)n * FT);
        ap[2 * lane]     = make_float4(acc[0], acc[1], acc[2], acc[3]);
        ap[2 * lane + 1] = make_float4(acc[4], acc[5], acc[6], acc[7]);
    }
}

// Half-width (16 columns) gate pre-activation into t2[8] packed pairs:
//   t2 = c[hf] + sum_f a[f]*A[f][hf] + sum_k v[k]*B[k][hf]
__device__ __forceinline__ void gate_half(
    u64* t2,
    const float4 (*A)[HID / 4], const float4 (*B)[HID / 4],
    const float4* cvec, const float* a, const float* v, int hf)
{
    #pragma unroll
    for (int j4 = 0; j4 < 4; j4++) {
        F4U2 c; c.f4 = cvec[hf * 4 + j4];
        t2[2 * j4] = c.u[0]; t2[2 * j4 + 1] = c.u[1];
    }
    #pragma unroll 4
    for (int f = 0; f < FIN; f++) {
        u64 av = pk2(a[f], a[f]);
        #pragma unroll
        for (int j4 = 0; j4 < 4; j4++) {
            F4U2 w; w.f4 = A[f][hf * 4 + j4];
            t2[2 * j4]     = fma2(av, w.u[0], t2[2 * j4]);
            t2[2 * j4 + 1] = fma2(av, w.u[1], t2[2 * j4 + 1]);
        }
    }
    #pragma unroll 4
    for (int k = 0; k < HID; k++) {
        u64 hk = pk2(v[k], v[k]);
        #pragma unroll
        for (int j4 = 0; j4 < 4; j4++) {
            F4U2 w; w.f4 = B[k][hf * 4 + j4];
            t2[2 * j4]     = fma2(hk, w.u[0], t2[2 * j4]);
            t2[2 * j4 + 1] = fma2(hk, w.u[1], t2[2 * j4 + 1]);
        }
    }
}

// Per-node GRU over T=12 steps. Low register pressure version:
// stage order r -> candidate -> z, half-width temporaries, no Z/apk arrays.
__global__ void __launch_bounds__(128, 2)
k_gru(const float* __restrict__ LzW, const float* __restrict__ LrW,
      const float* __restrict__ LhW, int N) {
    __shared__ float4 sA[3][FIN][HID / 4];   // folded A matrices
    __shared__ float4 sB[3][HID][HID / 4];   // bottom halves of L matrices
    __shared__ float4 sc[3][HID / 4];        // folded biases
    __shared__ float  sp[TT];
    __shared__ float  bsum[HID];

    int tid = threadIdx.x;
    {
        float* pA = (float*)sA;
        for (int i = tid; i < 3 * FIN * HID; i += 128) pA[i] = g_A[i];
        float* pB = (float*)sB;
        for (int i = tid; i < HID * HID; i += 128) {
            pB[i]                 = LzW[HID * HID + i];
            pB[HID * HID + i]     = LrW[HID * HID + i];
            pB[2 * HID * HID + i] = LhW[HID * HID + i];
        }
        float* pc = (float*)sc;
        if (tid < 3 * HID) pc[tid] = g_c[tid];
        if (tid < TT) sp[tid] = g_probs[tid];
        if (tid < HID) bsum[tid] = 0.0f;
    }
    __syncthreads();

    int n = blockIdx.x * 128 + tid;
    if (n < N) {
        float H[HID], acc[HID];
        #pragma unroll
        for (int j = 0; j < HID; j++) { H[j] = 0.0f; acc[j] = 0.0f; }
        const float4* ap4 = (const float4*)(g_agg + (size_t)n * FT);

        #pragma unroll 1
        for (int t = 0; t < TT; t++) {
            float a[FIN];
            {
                float4 a0 = __ldg(&ap4[4 * t + 0]);
                float4 a1 = __ldg(&ap4[4 * t + 1]);
                float4 a2 = __ldg(&ap4[4 * t + 2]);
                float4 a3 = __ldg(&ap4[4 * t + 3]);
                a[0]  = a0.x; a[1]  = a0.y; a[2]  = a0.z; a[3]  = a0.w;
                a[4]  = a1.x; a[5]  = a1.y; a[6]  = a1.z; a[7]  = a1.w;
                a[8]  = a2.x; a[9]  = a2.y; a[10] = a2.z; a[11] = a2.w;
                a[12] = a3.x; a[13] = a3.y; a[14] = a3.z; a[15] = a3.w;
            }
            float p = sp[t];

            // ---- r gate: R = sigmoid(r) * H  (needs H; halves) ----
            float R[HID];
            #pragma unroll
            for (int hf = 0; hf < 2; hf++) {
                u64 t2[8];
                gate_half(t2, sA[1], sB[1], sc[1], a, H, hf);
                #pragma unroll
                for (int j2 = 0; j2 < 8; j2++) {
                    float x0, x1;
                    up2(t2[j2], x0, x1);
                    int j = hf * 16 + 2 * j2;
                    R[j]     = sigf(x0) * H[j];
                    R[j + 1] = sigf(x1) * H[j + 1];
                }
            }

            // ---- candidate: HT = tanh(h(R))  (needs R; halves) ----
            float HT[HID];
            #pragma unroll
            for (int hf = 0; hf < 2; hf++) {
                u64 t2[8];
                gate_half(t2, sA[2], sB[2], sc[2], a, R, hf);
                #pragma unroll
                for (int j2 = 0; j2 < 8; j2++) {
                    float x0, x1;
                    up2(t2[j2], x0, x1);
                    int j = hf * 16 + 2 * j2;
                    HT[j]     = tanhfast(x0);
                    HT[j + 1] = tanhfast(x1);
                }
            }
            // R dead from here.

            // ---- z gate + state update (needs full old H as input) ----
            float ZP[16];
            {
                u64 t2[8];
                gate_half(t2, sA[0], sB[0], sc[0], a, H, 0);
                #pragma unroll
                for (int j2 = 0; j2 < 8; j2++)
                    up2(t2[j2], ZP[2 * j2], ZP[2 * j2 + 1]);
            }
            {
                u64 t2[8];
                gate_half(t2, sA[0], sB[0], sc[0], a, H, 1);
                // all reads of old H complete; update second half now
                #pragma unroll
                for (int j2 = 0; j2 < 8; j2++) {
                    float x0, x1;
                    up2(t2[j2], x0, x1);
                    int j = 16 + 2 * j2;
                    float z0 = sigf(x0), z1 = sigf(x1);
                    H[j]     = z0 * H[j]     + (1.0f - z0) * HT[j];
                    H[j + 1] = z1 * H[j + 1] + (1.0f - z1) * HT[j + 1];
                    acc[j]     = fmaf(p, H[j],     acc[j]);
                    acc[j + 1] = fmaf(p, H[j + 1], acc[j + 1]);
                }
            }
            #pragma unroll
            for (int j = 0; j < 16; j++) {
                float z = sigf(ZP[j]);
                H[j] = z * H[j] + (1.0f - z) * HT[j];
                acc[j] = fmaf(p, H[j], acc[j]);
            }
        }
        #pragma unroll
        for (int j = 0; j < HID; j++) {
            float v = acc[j] > 0.0f ? acc[j] : 0.0f;
            atomicAdd(&bsum[j], v);
        }
    }
    __syncthreads();
    if (tid < HID) atomicAdd(&g_hsum[tid], bsum[tid]);
}

__global__ void k_final(const float* __restrict__ linW, const float* __restrict__ linb,
                        float* out, int N) {
    int j = threadIdx.x;   // 32 threads
    float invN = 1.0f / (float)N;
    float v = g_hsum[j] * invN * linW[j];
    #pragma unroll
    for (int o = 16; o; o >>= 1) v += __shfl_xor_sync(0xffffffffu, v, o);
    if (j == 0) {
        float r = v + linb[0];
        out[0] = r > 0.0f ? r : 0.0f;
    }
}

// ---------------- launcher ----------------
extern "C" void kernel_launch(void* const* d_in, const int* in_sizes, int n_in,
                              void* d_out, int out_size) {
    const float* x    = (const float*)d_in[0];
    const int*   ei   = (const int*)  d_in[1];
    const float* att  = (const float*)d_in[2];
    const float* Wz   = (const float*)d_in[3];
    const float* bz   = (const float*)d_in[4];
    const float* Wr   = (const float*)d_in[5];
    const float* br   = (const float*)d_in[6];
    const float* Wh   = (const float*)d_in[7];
    const float* bh   = (const float*)d_in[8];
    const float* LzW  = (const float*)d_in[9];
    const float* Lzb  = (const float*)d_in[10];
    const float* LrW  = (const float*)d_in[11];
    const float* Lrb  = (const float*)d_in[12];
    const float* LhW  = (const float*)d_in[13];
    const float* Lhb  = (const float*)d_in[14];
    const float* linW = (const float*)d_in[15];
    const float* linb = (const float*)d_in[16];

    int N = in_sizes[0] / FT;
    int E = in_sizes[1] / 2;
    int NB = (N + SB - 1) / SB;

    // order chosen so launch #4 (the one ncu captures) is k_cnt — an unknown
    k_zero<<<(N + 255) / 256, 256>>>(N);
    k_half<<<(N + 3) / 4, 256>>>(x, N);
    k_prep<<<1, 512>>>(Wz, bz, Wr, br, Wh, bh, LzW, Lzb, LrW, Lrb, LhW, Lhb, att);
    k_cnt<<<(E + 255) / 256, 256>>>(ei, E);
    k_scan_a<<<NB, SB>>>(N);
    k_scan_b<<<1, 128>>>(NB, N, E);
    k_scan_c<<<NB, SB>>>(N);
    k_fill<<<(E + 255) / 256, 256>>>(ei, E);
    k_gather<<<(N * 32 + 255) / 256, 256>>>(N);
    k_gru<<<(N + 127) / 128, 128>>>(LzW, LrW, LhW, N);
    k_final<<<1, 32>>>(linW, linb, (float*)d_out, N);
}

// round 8
// speedup vs baseline: 1.5799x; 1.3155x over previous
#include <cuda_runtime.h>
#include <cuda_fp16.h>
#include <math.h>

#define NMAX 50000
#define EMAX 1600000
#define FIN 16
#define TT 12
#define HID 32
#define FT (FIN*TT)   // 192 values per node
#define SB 512        // scan block size

// ---------------- scratch (static device globals; no allocation) ----------------
__device__ int    g_cnt[NMAX];                    // in-degree counts (excl. self-loop)
__device__ int    g_rowptr[NMAX + 1];             // CSR row pointers
__device__ int    g_cur[NMAX];                    // fill cursors
__device__ int2   g_sw[EMAX];                     // CSR payload: {src, bits(norm weight)}
__device__ int    g_part[256];                    // scan partials
__device__ float  g_dis[NMAX];                    // rsqrt(degree incl. self-loop)
__device__ __half g_xh[(size_t)NMAX * FT];        // fp16 features, t-major [N][T][F]
__device__ float  g_agg[(size_t)NMAX * FT];       // aggregated features, t-major [N][T][F]
__device__ float  g_A[3 * FIN * HID];             // folded W_g @ L_g_top
__device__ float  g_c[3 * HID];                   // folded biases
__device__ float  g_probs[TT];                    // softmax(att)
__device__ float  g_hsum[HID];                    // sum over nodes of relu(Hacc)

// ---------------- helpers ----------------
__device__ __forceinline__ float sigf(float x) {
    return __fdividef(1.0f, 1.0f + __expf(-x));
}
__device__ __forceinline__ float tanhfast(float x) {
    return fmaf(2.0f, __fdividef(1.0f, 1.0f + __expf(-2.0f * x)), -1.0f);
}

// packed f32x2 helpers (Blackwell FFMA2)
typedef unsigned long long u64;
__device__ __forceinline__ u64 pk2(float x, float y) {
    u64 r; asm("mov.b64 %0, {%1,%2};" : "=l"(r) : "f"(x), "f"(y)); return r;
}
__device__ __forceinline__ u64 fma2(u64 a, u64 b, u64 c) {
    u64 d; asm("fma.rn.f32x2 %0, %1, %2, %3;" : "=l"(d) : "l"(a), "l"(b), "l"(c)); return d;
}
__device__ __forceinline__ void up2(u64 v, float& x, float& y) {
    asm("mov.b64 {%0,%1}, %2;" : "=f"(x), "=f"(y) : "l"(v));
}
union F4U2 { float4 f4; u64 u[2]; };
union F4H2 { float4 f4; __half2 h2[4]; };

// ---------------- kernels ----------------
__global__ void k_zero(int N) {
    int i = blockIdx.x * blockDim.x + threadIdx.x;
    if (i < N) g_cnt[i] = 0;
    if (i < HID) g_hsum[i] = 0.0f;
}

__global__ void k_cnt(const int* __restrict__ ei, int E) {
    int e = blockIdx.x * blockDim.x + threadIdx.x;
    if (e < E) atomicAdd(&g_cnt[ei[E + e]], 1);
}

// Convert x [N][F][T] fp32 -> g_xh [N][T][F] fp16. 4 nodes per block of 256.
__global__ void k_half(const float* __restrict__ x, int N) {
    __shared__ float sx[4 * FT];
    int tid = threadIdx.x;
    size_t base = (size_t)blockIdx.x * 4 * FT;
    size_t lim  = (size_t)N * FT;
    #pragma unroll
    for (int i = tid; i < 4 * FT; i += 256) {
        size_t g = base + i;
        if (g < lim) sx[i] = x[g];
    }
    __syncthreads();
    #pragma unroll
    for (int i = tid; i < 4 * FT; i += 256) {
        size_t g = base + i;
        if (g < lim) {
            int nn = i / FT, p = i % FT;
            int t = p / FIN, f = p % FIN;
            g_xh[g] = __float2half(sx[nn * FT + f * TT + t]);
        }
    }
}

// Precompute folded matrices A_g = W_g @ L_g[0:32,:], c_g = b_g @ L_g[0:32,:] + Lgb,
// and softmax(att). One block of 512 threads.
__global__ void k_prep(const float* __restrict__ Wz, const float* __restrict__ bz,
                       const float* __restrict__ Wr, const float* __restrict__ br,
                       const float* __restrict__ Wh, const float* __restrict__ bh,
                       const float* __restrict__ LzW, const float* __restrict__ Lzb,
                       const float* __restrict__ LrW, const float* __restrict__ Lrb,
                       const float* __restrict__ LhW, const float* __restrict__ Lhb,
                       const float* __restrict__ att) {
    int id = threadIdx.x;                       // 512 threads
    const float* W[3]  = {Wz, Wr, Wh};
    const float* L[3]  = {LzW, LrW, LhW};
    const float* bb[3] = {bz, br, bh};
    const float* Lb[3] = {Lzb, Lrb, Lhb};

    int f = id >> 5, j = id & 31;               // 16 x 32 = 512
    #pragma unroll
    for (int g = 0; g < 3; g++) {
        float s = 0.0f;
        #pragma unroll
        for (int k = 0; k < HID; k++)
            s = fmaf(__ldg(&W[g][f * HID + k]), __ldg(&L[g][k * HID + j]), s);
        g_A[(g * FIN + f) * HID + j] = s;
    }
    if (id < 3 * HID) {
        int g = id >> 5, jj = id & 31;
        float s = __ldg(&Lb[g][jj]);
        #pragma unroll
        for (int k = 0; k < HID; k++)
            s = fmaf(__ldg(&bb[g][k]), __ldg(&L[g][k * HID + jj]), s);
        g_c[g * HID + jj] = s;
    }
    if (id < 32) {
        float v = (id < TT) ? __ldg(&att[id]) : -1e30f;
        float m = v;
        #pragma unroll
        for (int o = 16; o; o >>= 1) m = fmaxf(m, __shfl_xor_sync(0xffffffffu, m, o));
        float e = (id < TT) ? __expf(v - m) : 0.0f;
        float s = e;
        #pragma unroll
        for (int o = 16; o; o >>= 1) s += __shfl_xor_sync(0xffffffffu, s, o);
        if (id < TT) g_probs[id] = e * __fdividef(1.0f, s);
    }
}

// ---- parallel 3-phase scan ----
__global__ void k_scan_a(int N) {
    __shared__ int ws[SB / 32];
    int tid = threadIdx.x;
    int i = blockIdx.x * SB + tid;
    int v = (i < N) ? g_cnt[i] : 0;
    #pragma unroll
    for (int o = 16; o; o >>= 1) v += __shfl_xor_sync(0xffffffffu, v, o);
    if ((tid & 31) == 0) ws[tid >> 5] = v;
    __syncthreads();
    if (tid < SB / 32) {
        int w = ws[tid];
        #pragma unroll
        for (int o = 8; o; o >>= 1) w += __shfl_xor_sync(0xffffu, w, o);
        if (tid == 0) g_part[blockIdx.x] = w;
    }
}

__global__ void k_scan_b(int NB, int N, int E) {
    __shared__ int ws[4];
    int tid = threadIdx.x, lane = tid & 31, wid = tid >> 5;
    int orig = (tid < NB) ? g_part[tid] : 0;
    int v = orig;
    #pragma unroll
    for (int o = 1; o < 32; o <<= 1) {
        int t = __shfl_up_sync(0xffffffffu, v, o);
        if (lane >= o) v += t;
    }
    if (lane == 31) ws[wid] = v;
    __syncthreads();
    if (wid == 0 && lane < 4) {
        int w = ws[lane];
        #pragma unroll
        for (int o = 1; o < 4; o <<= 1) {
            int t = __shfl_up_sync(0xfu, w, o);
            if (lane >= o) w += t;
        }
        ws[lane] = w;
    }
    __syncthreads();
    int incl = v + (wid > 0 ? ws[wid - 1] : 0);
    if (tid < NB) g_part[tid] = incl - orig;     // exclusive
    if (tid == 0) g_rowptr[N] = E;
}

__global__ void k_scan_c(int N) {
    __shared__ int ws[SB / 32];
    int tid = threadIdx.x, lane = tid & 31, wid = tid >> 5;
    int i = blockIdx.x * SB + tid;
    int c = (i < N) ? g_cnt[i] : 0;
    int v = c;
    #pragma unroll
    for (int o = 1; o < 32; o <<= 1) {
        int t = __shfl_up_sync(0xffffffffu, v, o);
        if (lane >= o) v += t;
    }
    if (lane == 31) ws[wid] = v;
    __syncthreads();
    if (wid == 0 && lane < SB / 32) {
        int w = ws[lane];
        #pragma unroll
        for (int o = 1; o < SB / 32; o <<= 1) {
            int t = __shfl_up_sync((1u << (SB / 32)) - 1u, w, o);
            if (lane >= o) w += t;
        }
        ws[lane] = w;
    }
    __syncthreads();
    int excl = v - c + (wid > 0 ? ws[wid - 1] : 0) + g_part[blockIdx.x];
    if (i < N) {
        g_rowptr[i] = excl;
        g_cur[i]    = excl;
        g_dis[i]    = rsqrtf((float)(c + 1));    // +1 self-loop
    }
}

// CSR fill with folded norm weight: payload {src, dis[s]*dis[d]}
__global__ void k_fill(const int* __restrict__ ei, int E) {
    int e = blockIdx.x * blockDim.x + threadIdx.x;
    if (e >= E) return;
    int s = ei[e];
    int d = ei[E + e];
    int p = atomicAdd(&g_cur[d], 1);
    g_sw[p] = make_int2(s, __float_as_int(g_dis[s] * g_dis[d]));
}

// Warp-per-node gather on fp16 features (fp32 accumulation).
__global__ void __launch_bounds__(256)
k_gather(int N) {
    __shared__ int2 stage[8][32];
    int gw   = (blockIdx.x * blockDim.x + threadIdx.x) >> 5;
    int wloc = threadIdx.x >> 5;
    int lane = threadIdx.x & 31;
    if (gw >= N) return;
    int n = gw;

    int beg = g_rowptr[n];
    int end = g_rowptr[n + 1];
    float dd = g_dis[n];
    int ln = (lane < 24) ? lane : 0;        // clamped payload lane

    float acc[8];
    {
        float inv = dd * dd;                       // 1/deg (self-loop term)
        F4H2 v; v.f4 = ((const float4*)(g_xh + (size_t)n * FT))[ln];
        #pragma unroll
        for (int q = 0; q < 4; q++) {
            float2 f = __half22float2(v.h2[q]);
            acc[2 * q]     = inv * f.x;
            acc[2 * q + 1] = inv * f.y;
        }
    }

    for (int i = beg; i < end; i += 32) {
        int j = i + lane;
        if (j < end) stage[wloc][lane] = g_sw[j];
        __syncwarp();
        int m = min(32, end - i);
        #pragma unroll 8
        for (int u = 0; u < m; u++) {
            int2 sw = stage[wloc][u];
            float ww = __int_as_float(sw.y);
            F4H2 v; v.f4 = ((const float4*)(g_xh + (size_t)sw.x * FT))[ln];
            #pragma unroll
            for (int q = 0; q < 4; q++) {
                float2 f = __half22float2(v.h2[q]);
                acc[2 * q]     = fmaf(ww, f.x, acc[2 * q]);
                acc[2 * q + 1] = fmaf(ww, f.y, acc[2 * q + 1]);
            }
        }
        __syncwarp();
    }

    if (lane < 24) {
        float4* ap = (float4*)(g_agg + (size_t)n * FT);
        ap[2 * lane]     = make_float4(acc[0], acc[1], acc[2], acc[3]);
        ap[2 * lane + 1] = make_float4(acc[4], acc[5], acc[6], acc[7]);
    }
}

// ---- 2-threads-per-node GRU ----
// Thread owns 16 of 32 hidden columns (half = lane&1). Partner's state values
// are fetched via shfl_xor(.,1) inside the k-loop, so no full-width arrays.
// Gate pre-activation for the own 16 columns into t2[8] packed pairs:
//   t2 = c[own] + sum_f a[f]*A[f][own] + sum_k v_full[k]*B[k][own]
// where v_full = (own half from vown regs, other half via shfl).
__device__ __forceinline__ void gate2(
    u64* t2,
    const float4 (*A)[HID / 4], const float4 (*B)[HID / 4],
    const float4* cvec, const float* a, const float* vown,
    int jb /* own float4 base: 0 or 4 */, int kown /* own k base: 0 or 16 */)
{
    #pragma unroll
    for (int j4 = 0; j4 < 4; j4++) {
        F4U2 c; c.f4 = cvec[jb + j4];
        t2[2 * j4] = c.u[0]; t2[2 * j4 + 1] = c.u[1];
    }
    #pragma unroll 4
    for (int f = 0; f < FIN; f++) {
        u64 av = pk2(a[f], a[f]);
        #pragma unroll
        for (int j4 = 0; j4 < 4; j4++) {
            F4U2 w; w.f4 = A[f][jb + j4];
            t2[2 * j4]     = fma2(av, w.u[0], t2[2 * j4]);
            t2[2 * j4 + 1] = fma2(av, w.u[1], t2[2 * j4 + 1]);
        }
    }
    int koth = 16 - kown;
    #pragma unroll 4
    for (int k2 = 0; k2 < 16; k2++) {
        // own-half k
        {
            float v = vown[k2];
            u64 hk = pk2(v, v);
            #pragma unroll
            for (int j4 = 0; j4 < 4; j4++) {
                F4U2 w; w.f4 = B[kown + k2][jb + j4];
                t2[2 * j4]     = fma2(hk, w.u[0], t2[2 * j4]);
                t2[2 * j4 + 1] = fma2(hk, w.u[1], t2[2 * j4 + 1]);
            }
        }
        // partner-half k (exchange one value)
        {
            float v = __shfl_xor_sync(0xffffffffu, vown[k2], 1);
            u64 hk = pk2(v, v);
            #pragma unroll
            for (int j4 = 0; j4 < 4; j4++) {
                F4U2 w; w.f4 = B[koth + k2][jb + j4];
                t2[2 * j4]     = fma2(hk, w.u[0], t2[2 * j4]);
                t2[2 * j4 + 1] = fma2(hk, w.u[1], t2[2 * j4 + 1]);
            }
        }
    }
}

__global__ void __launch_bounds__(128)
k_gru(const float* __restrict__ LzW, const float* __restrict__ LrW,
      const float* __restrict__ LhW, int N) {
    __shared__ float4 sA[3][FIN][HID / 4];   // folded A matrices
    __shared__ float4 sB[3][HID][HID / 4];   // bottom halves of L matrices
    __shared__ float4 sc[3][HID / 4];        // folded biases
    __shared__ float  sp[TT];
    __shared__ float  bsum[HID];

    int tid = threadIdx.x;
    {
        float* pA = (float*)sA;
        for (int i = tid; i < 3 * FIN * HID; i += 128) pA[i] = g_A[i];
        float* pB = (float*)sB;
        for (int i = tid; i < HID * HID; i += 128) {
            pB[i]                 = LzW[HID * HID + i];
            pB[HID * HID + i]     = LrW[HID * HID + i];
            pB[2 * HID * HID + i] = LhW[HID * HID + i];
        }
        float* pc = (float*)sc;
        if (tid < 3 * HID) pc[tid] = g_c[tid];
        if (tid < TT) sp[tid] = g_probs[tid];
        if (tid < HID) bsum[tid] = 0.0f;
    }
    __syncthreads();

    // 64 nodes per block; threads (2m, 2m+1) handle node m's two column halves
    int gt   = blockIdx.x * 64 * 2 + tid;
    int node = gt >> 1;
    int half = gt & 1;
    bool live = node < N;
    int n  = live ? node : (N - 1);          // clamp: dead threads compute on valid data
    int jb = half * 4;                        // own float4 base within row of 8
    int kown = half * 16;                     // own k range base
    int jo = half * 16;                       // own column offset

    float H[16], acc[16];
    #pragma unroll
    for (int j = 0; j < 16; j++) { H[j] = 0.0f; acc[j] = 0.0f; }
    const float4* ap4 = (const float4*)(g_agg + (size_t)n * FT);

    #pragma unroll 1
    for (int t = 0; t < TT; t++) {
        float a[FIN];
        {
            float4 a0 = __ldg(&ap4[4 * t + 0]);
            float4 a1 = __ldg(&ap4[4 * t + 1]);
            float4 a2 = __ldg(&ap4[4 * t + 2]);
            float4 a3 = __ldg(&ap4[4 * t + 3]);
            a[0]  = a0.x; a[1]  = a0.y; a[2]  = a0.z; a[3]  = a0.w;
            a[4]  = a1.x; a[5]  = a1.y; a[6]  = a1.z; a[7]  = a1.w;
            a[8]  = a2.x; a[9]  = a2.y; a[10] = a2.z; a[11] = a2.w;
            a[12] = a3.x; a[13] = a3.y; a[14] = a3.z; a[15] = a3.w;
        }
        float p = sp[t];
        u64 t2[8];

        // ---- r gate: R = sigmoid(r) * H (own 16 cols) ----
        float R[16];
        gate2(t2, sA[1], sB[1], sc[1], a, H, jb, kown);
        #pragma unroll
        for (int j2 = 0; j2 < 8; j2++) {
            float x0, x1;
            up2(t2[j2], x0, x1);
            R[2 * j2]     = sigf(x0) * H[2 * j2];
            R[2 * j2 + 1] = sigf(x1) * H[2 * j2 + 1];
        }

        // ---- candidate: HT = tanh(h(R)) ----
        float HT[16];
        gate2(t2, sA[2], sB[2], sc[2], a, R, jb, kown);
        #pragma unroll
        for (int j2 = 0; j2 < 8; j2++) {
            float x0, x1;
            up2(t2[j2], x0, x1);
            HT[2 * j2]     = tanhfast(x0);
            HT[2 * j2 + 1] = tanhfast(x1);
        }

        // ---- z gate + state update ----
        gate2(t2, sA[0], sB[0], sc[0], a, H, jb, kown);
        #pragma unroll
        for (int j2 = 0; j2 < 8; j2++) {
            float x0, x1;
            up2(t2[j2], x0, x1);
            int j = 2 * j2;
            float z0 = sigf(x0), z1 = sigf(x1);
            H[j]     = z0 * H[j]     + (1.0f - z0) * HT[j];
            H[j + 1] = z1 * H[j + 1] + (1.0f - z1) * HT[j + 1];
            acc[j]     = fmaf(p, H[j],     acc[j]);
            acc[j + 1] = fmaf(p, H[j + 1], acc[j + 1]);
        }
    }

    if (live) {
        #pragma unroll
        for (int j = 0; j < 16; j++) {
            float v = acc[j] > 0.0f ? acc[j] : 0.0f;
            atomicAdd(&bsum[jo + j], v);
        }
    }
    __syncthreads();
    if (tid < HID) atomicAdd(&g_hsum[tid], bsum[tid]);
}

__global__ void k_final(const float* __restrict__ linW, const float* __restrict__ linb,
                        float* out, int N) {
    int j = threadIdx.x;   // 32 threads
    float invN = 1.0f / (float)N;
    float v = g_hsum[j] * invN * linW[j];
    #pragma unroll
    for (int o = 16; o; o >>= 1) v += __shfl_xor_sync(0xffffffffu, v, o);
    if (j == 0) {
        float r = v + linb[0];
        out[0] = r > 0.0f ? r : 0.0f;
    }
}

// ---------------- launcher ----------------
extern "C" void kernel_launch(void* const* d_in, const int* in_sizes, int n_in,
                              void* d_out, int out_size) {
    const float* x    = (const float*)d_in[0];
    const int*   ei   = (const int*)  d_in[1];
    const float* att  = (const float*)d_in[2];
    const float* Wz   = (const float*)d_in[3];
    const float* bz   = (const float*)d_in[4];
    const float* Wr   = (const float*)d_in[5];
    const float* br   = (const float*)d_in[6];
    const float* Wh   = (const float*)d_in[7];
    const float* bh   = (const float*)d_in[8];
    const float* LzW  = (const float*)d_in[9];
    const float* Lzb  = (const float*)d_in[10];
    const float* LrW  = (const float*)d_in[11];
    const float* Lrb  = (const float*)d_in[12];
    const float* LhW  = (const float*)d_in[13];
    const float* Lhb  = (const float*)d_in[14];
    const float* linW = (const float*)d_in[15];
    const float* linb = (const float*)d_in[16];

    int N = in_sizes[0] / FT;
    int E = in_sizes[1] / 2;
    int NB = (N + SB - 1) / SB;

    // order chosen so launch #4 (the one ncu captures) is k_half — an unknown
    k_zero<<<(N + 255) / 256, 256>>>(N);
    k_cnt<<<(E + 255) / 256, 256>>>(ei, E);
    k_prep<<<1, 512>>>(Wz, bz, Wr, br, Wh, bh, LzW, Lzb, LrW, Lrb, LhW, Lhb, att);
    k_half<<<(N + 3) / 4, 256>>>(x, N);
    k_scan_a<<<NB, SB>>>(N);
    k_scan_b<<<1, 128>>>(NB, N, E);
    k_scan_c<<<NB, SB>>>(N);
    k_fill<<<(E + 255) / 256, 256>>>(ei, E);
    k_gather<<<(N * 32 + 255) / 256, 256>>>(N);
    k_gru<<<(N * 2 + 127) / 128, 128>>>(LzW, LrW, LhW, N);
    k_final<<<1, 32>>>(linW, linb, (float*)d_out, N);
}

// round 9
// speedup vs baseline: 2.0688x; 1.3094x over previous
#include <cuda_runtime.h>
#include <cuda_fp16.h>
#include <math.h>

#define NMAX 50000
#define EMAX 1600000
#define FIN 16
#define TT 12
#define HID 32
#define FT (FIN*TT)   // 192 values per node
#define SB 512        // scan block size

// ---------------- scratch (static device globals; no allocation) ----------------
__device__ int    g_cnt[NMAX];                    // in-degree counts (excl. self-loop); zeroed by k_fill each run
__device__ int    g_rowptr[NMAX + 1];             // CSR row pointers
__device__ int    g_cur[NMAX];                    // fill cursors
__device__ int2   g_sw[EMAX];                     // CSR payload: {src, bits(norm weight)}
__device__ int    g_part[256];                    // scan partials
__device__ float  g_dis[NMAX];                    // rsqrt(degree incl. self-loop)
__device__ __half g_xh[(size_t)NMAX * FT];        // fp16 features, t-major [N][T][F]
__device__ float  g_agg[(size_t)NMAX * FT];       // aggregated features, t-major [N][T][F]
__device__ float  g_A[3 * FIN * HID];             // folded W_g @ L_g_top
__device__ float  g_c[3 * HID];                   // folded biases
__device__ float  g_probs[TT];                    // softmax(att)
__device__ float  g_hsum[HID];                    // sum over nodes of relu(Hacc); zeroed by k_final each run

// ---------------- helpers ----------------
__device__ __forceinline__ float sigf(float x) {
    return __fdividef(1.0f, 1.0f + __expf(-x));
}
__device__ __forceinline__ float tanhfast(float x) {
    return fmaf(2.0f, __fdividef(1.0f, 1.0f + __expf(-2.0f * x)), -1.0f);
}

// packed f32x2 helpers (Blackwell FFMA2)
typedef unsigned long long u64;
__device__ __forceinline__ u64 pk2(float x, float y) {
    u64 r; asm("mov.b64 %0, {%1,%2};" : "=l"(r) : "f"(x), "f"(y)); return r;
}
__device__ __forceinline__ u64 fma2(u64 a, u64 b, u64 c) {
    u64 d; asm("fma.rn.f32x2 %0, %1, %2, %3;" : "=l"(d) : "l"(a), "l"(b), "l"(c)); return d;
}
__device__ __forceinline__ void up2(u64 v, float& x, float& y) {
    asm("mov.b64 {%0,%1}, %2;" : "=f"(x), "=f"(y) : "l"(v));
}
union F4U2 { float4 f4; u64 u[2]; };
union F4H2 { float4 f4; __half2 h2[4]; };

// ---------------- kernels ----------------
__global__ void k_cnt(const int* __restrict__ ei, int E) {
    int e = blockIdx.x * blockDim.x + threadIdx.x;
    if (e < E) atomicAdd(&g_cnt[ei[E + e]], 1);
}

// Convert x [N][F][T] fp32 -> g_xh [N][T][F] fp16. 4 nodes per block of 256.
__global__ void k_half(const float* __restrict__ x, int N) {
    __shared__ float sx[4 * FT];
    int tid = threadIdx.x;
    size_t base = (size_t)blockIdx.x * 4 * FT;
    size_t lim  = (size_t)N * FT;
    #pragma unroll
    for (int i = tid; i < 4 * FT; i += 256) {
        size_t g = base + i;
        if (g < lim) sx[i] = x[g];
    }
    __syncthreads();
    #pragma unroll
    for (int i = tid; i < 4 * FT; i += 256) {
        size_t g = base + i;
        if (g < lim) {
            int nn = i / FT, p = i % FT;
            int t = p / FIN, f = p % FIN;
            g_xh[g] = __float2half(sx[nn * FT + f * TT + t]);
        }
    }
}

// Precompute folded matrices A_g = W_g @ L_g[0:32,:], c_g = b_g @ L_g[0:32,:] + Lgb,
// and softmax(att). One block of 512 threads.
__global__ void k_prep(const float* __restrict__ Wz, const float* __restrict__ bz,
                       const float* __restrict__ Wr, const float* __restrict__ br,
                       const float* __restrict__ Wh, const float* __restrict__ bh,
                       const float* __restrict__ LzW, const float* __restrict__ Lzb,
                       const float* __restrict__ LrW, const float* __restrict__ Lrb,
                       const float* __restrict__ LhW, const float* __restrict__ Lhb,
                       const float* __restrict__ att) {
    int id = threadIdx.x;                       // 512 threads
    const float* W[3]  = {Wz, Wr, Wh};
    const float* L[3]  = {LzW, LrW, LhW};
    const float* bb[3] = {bz, br, bh};
    const float* Lb[3] = {Lzb, Lrb, Lhb};

    int f = id >> 5, j = id & 31;               // 16 x 32 = 512
    #pragma unroll
    for (int g = 0; g < 3; g++) {
        float s = 0.0f;
        #pragma unroll
        for (int k = 0; k < HID; k++)
            s = fmaf(__ldg(&W[g][f * HID + k]), __ldg(&L[g][k * HID + j]), s);
        g_A[(g * FIN + f) * HID + j] = s;
    }
    if (id < 3 * HID) {
        int g = id >> 5, jj = id & 31;
        float s = __ldg(&Lb[g][jj]);
        #pragma unroll
        for (int k = 0; k < HID; k++)
            s = fmaf(__ldg(&bb[g][k]), __ldg(&L[g][k * HID + jj]), s);
        g_c[g * HID + jj] = s;
    }
    if (id < 32) {
        float v = (id < TT) ? __ldg(&att[id]) : -1e30f;
        float m = v;
        #pragma unroll
        for (int o = 16; o; o >>= 1) m = fmaxf(m, __shfl_xor_sync(0xffffffffu, m, o));
        float e = (id < TT) ? __expf(v - m) : 0.0f;
        float s = e;
        #pragma unroll
        for (int o = 16; o; o >>= 1) s += __shfl_xor_sync(0xffffffffu, s, o);
        if (id < TT) g_probs[id] = e * __fdividef(1.0f, s);
    }
}

// ---- parallel 3-phase scan ----
__global__ void k_scan_a(int N) {
    __shared__ int ws[SB / 32];
    int tid = threadIdx.x;
    int i = blockIdx.x * SB + tid;
    int v = (i < N) ? g_cnt[i] : 0;
    #pragma unroll
    for (int o = 16; o; o >>= 1) v += __shfl_xor_sync(0xffffffffu, v, o);
    if ((tid & 31) == 0) ws[tid >> 5] = v;
    __syncthreads();
    if (tid < SB / 32) {
        int w = ws[tid];
        #pragma unroll
        for (int o = 8; o; o >>= 1) w += __shfl_xor_sync(0xffffu, w, o);
        if (tid == 0) g_part[blockIdx.x] = w;
    }
}

__global__ void k_scan_b(int NB, int N, int E) {
    __shared__ int ws[4];
    int tid = threadIdx.x, lane = tid & 31, wid = tid >> 5;
    int orig = (tid < NB) ? g_part[tid] : 0;
    int v = orig;
    #pragma unroll
    for (int o = 1; o < 32; o <<= 1) {
        int t = __shfl_up_sync(0xffffffffu, v, o);
        if (lane >= o) v += t;
    }
    if (lane == 31) ws[wid] = v;
    __syncthreads();
    if (wid == 0 && lane < 4) {
        int w = ws[lane];
        #pragma unroll
        for (int o = 1; o < 4; o <<= 1) {
            int t = __shfl_up_sync(0xfu, w, o);
            if (lane >= o) w += t;
        }
        ws[lane] = w;
    }
    __syncthreads();
    int incl = v + (wid > 0 ? ws[wid - 1] : 0);
    if (tid < NB) g_part[tid] = incl - orig;     // exclusive
    if (tid == 0) g_rowptr[N] = E;
}

__global__ void k_scan_c(int N) {
    __shared__ int ws[SB / 32];
    int tid = threadIdx.x, lane = tid & 31, wid = tid >> 5;
    int i = blockIdx.x * SB + tid;
    int c = (i < N) ? g_cnt[i] : 0;
    int v = c;
    #pragma unroll
    for (int o = 1; o < 32; o <<= 1) {
        int t = __shfl_up_sync(0xffffffffu, v, o);
        if (lane >= o) v += t;
    }
    if (lane == 31) ws[wid] = v;
    __syncthreads();
    if (wid == 0 && lane < SB / 32) {
        int w = ws[lane];
        #pragma unroll
        for (int o = 1; o < SB / 32; o <<= 1) {
            int t = __shfl_up_sync((1u << (SB / 32)) - 1u, w, o);
            if (lane >= o) w += t;
        }
        ws[lane] = w;
    }
    __syncthreads();
    int excl = v - c + (wid > 0 ? ws[wid - 1] : 0) + g_part[blockIdx.x];
    if (i < N) {
        g_rowptr[i] = excl;
        g_cur[i]    = excl;
        g_dis[i]    = rsqrtf((float)(c + 1));    // +1 self-loop
    }
}

// CSR fill with folded norm weight; also re-zeros g_cnt for the next replay
// (g_cnt is dead after k_scan_c; must be zero when the next run's k_cnt starts).
__global__ void k_fill(const int* __restrict__ ei, int E, int N) {
    int e = blockIdx.x * blockDim.x + threadIdx.x;
    if (e < N) g_cnt[e] = 0;
    if (e >= E) return;
    int s = ei[e];
    int d = ei[E + e];
    int p = atomicAdd(&g_cur[d], 1);
    g_sw[p] = make_int2(s, __float_as_int(g_dis[s] * g_dis[d]));
}

// Warp-per-node gather on fp16 features (fp32 accumulation).
__global__ void __launch_bounds__(256)
k_gather(int N) {
    __shared__ int2 stage[8][32];
    int gw   = (blockIdx.x * blockDim.x + threadIdx.x) >> 5;
    int wloc = threadIdx.x >> 5;
    int lane = threadIdx.x & 31;
    if (gw >= N) return;
    int n = gw;

    int beg = g_rowptr[n];
    int end = g_rowptr[n + 1];
    float dd = g_dis[n];
    int ln = (lane < 24) ? lane : 0;        // clamped payload lane

    float acc[8];
    {
        float inv = dd * dd;                       // 1/deg (self-loop term)
        F4H2 v; v.f4 = ((const float4*)(g_xh + (size_t)n * FT))[ln];
        #pragma unroll
        for (int q = 0; q < 4; q++) {
            float2 f = __half22float2(v.h2[q]);
            acc[2 * q]     = inv * f.x;
            acc[2 * q + 1] = inv * f.y;
        }
    }

    for (int i = beg; i < end; i += 32) {
        int j = i + lane;
        if (j < end) stage[wloc][lane] = g_sw[j];
        __syncwarp();
        int m = min(32, end - i);
        #pragma unroll 8
        for (int u = 0; u < m; u++) {
            int2 sw = stage[wloc][u];
            float ww = __int_as_float(sw.y);
            F4H2 v; v.f4 = ((const float4*)(g_xh + (size_t)sw.x * FT))[ln];
            #pragma unroll
            for (int q = 0; q < 4; q++) {
                float2 f = __half22float2(v.h2[q]);
                acc[2 * q]     = fmaf(ww, f.x, acc[2 * q]);
                acc[2 * q + 1] = fmaf(ww, f.y, acc[2 * q + 1]);
            }
        }
        __syncwarp();
    }

    if (lane < 24) {
        float4* ap = (float4*)(g_agg + (size_t)n * FT);
        ap[2 * lane]     = make_float4(acc[0], acc[1], acc[2], acc[3]);
        ap[2 * lane + 1] = make_float4(acc[4], acc[5], acc[6], acc[7]);
    }
}

// ---- M=4 node-blocked GRU ----
// Group of 4 lanes handles 4 nodes. Lane q (=tid&3) owns columns [8q, 8q+8)
// of ALL 4 nodes. Each weight LDS.128 is therefore amortized over 4 nodes
// (4x less smem crossbar traffic than 1-node-per-thread variants).
// Cross-lane a / H / R values come via compile-time-indexed shfl.
__device__ __forceinline__ void gate4(
    u64 t2[4][4],
    const float4 (*A)[HID / 4], const float4 (*B)[HID / 4], const float4* cv,
    const float a[4][4], const float Vin[4][8],
    int q2 /* = 2*q */, int lanebase)
{
    F4U2 c0, c1; c0.f4 = cv[q2]; c1.f4 = cv[q2 + 1];
    #pragma unroll
    for (int m = 0; m < 4; m++) {
        t2[m][0] = c0.u[0]; t2[m][1] = c0.u[1];
        t2[m][2] = c1.u[0]; t2[m][3] = c1.u[1];
    }
    #pragma unroll 4
    for (int f = 0; f < FIN; f++) {
        F4U2 w0, w1; w0.f4 = A[f][q2]; w1.f4 = A[f][q2 + 1];
        int src = lanebase + (f >> 2);
        #pragma unroll
        for (int m = 0; m < 4; m++) {
            float av = __shfl_sync(0xffffffffu, a[m][f & 3], src);
            u64 ap = pk2(av, av);
            t2[m][0] = fma2(ap, w0.u[0], t2[m][0]);
            t2[m][1] = fma2(ap, w0.u[1], t2[m][1]);
            t2[m][2] = fma2(ap, w1.u[0], t2[m][2]);
            t2[m][3] = fma2(ap, w1.u[1], t2[m][3]);
        }
    }
    #pragma unroll 8
    for (int k = 0; k < HID; k++) {
        F4U2 w0, w1; w0.f4 = B[k][q2]; w1.f4 = B[k][q2 + 1];
        int src = lanebase + (k >> 3);
        #pragma unroll
        for (int m = 0; m < 4; m++) {
            float hv = __shfl_sync(0xffffffffu, Vin[m][k & 7], src);
            u64 hp = pk2(hv, hv);
            t2[m][0] = fma2(hp, w0.u[0], t2[m][0]);
            t2[m][1] = fma2(hp, w0.u[1], t2[m][1]);
            t2[m][2] = fma2(hp, w1.u[0], t2[m][2]);
            t2[m][3] = fma2(hp, w1.u[1], t2[m][3]);
        }
    }
}

__global__ void __launch_bounds__(128)
k_gru(const float* __restrict__ LzW, const float* __restrict__ LrW,
      const float* __restrict__ LhW, int N) {
    __shared__ float4 sA[3][FIN][HID / 4];   // folded A matrices
    __shared__ float4 sB[3][HID][HID / 4];   // bottom halves of L matrices
    __shared__ float4 sc[3][HID / 4];        // folded biases
    __shared__ float  sp[TT];
    __shared__ float  bsum[HID];

    int tid = threadIdx.x;
    {
        float* pA = (float*)sA;
        for (int i = tid; i < 3 * FIN * HID; i += 128) pA[i] = g_A[i];
        float* pB = (float*)sB;
        for (int i = tid; i < HID * HID; i += 128) {
            pB[i]                 = LzW[HID * HID + i];
            pB[HID * HID + i]     = LrW[HID * HID + i];
            pB[2 * HID * HID + i] = LhW[HID * HID + i];
        }
        float* pc = (float*)sc;
        if (tid < 3 * HID) pc[tid] = g_c[tid];
        if (tid < TT) sp[tid] = g_probs[tid];
        if (tid < HID) bsum[tid] = 0.0f;
    }
    __syncthreads();

    int q  = tid & 3;
    int q2 = 2 * q;
    int lanebase = (tid & 31) & ~3;
    int grp  = blockIdx.x * 32 + (tid >> 2);   // 32 groups per 128-thread block
    int base = grp * 4;                         // first node of this group

    float H[4][8], acc[4][8];
    #pragma unroll
    for (int m = 0; m < 4; m++)
        #pragma unroll
        for (int j = 0; j < 8; j++) { H[m][j] = 0.0f; acc[m][j] = 0.0f; }

    #pragma unroll 1
    for (int t = 0; t < TT; t++) {
        float a[4][4];
        #pragma unroll
        for (int m = 0; m < 4; m++) {
            int nm = min(base + m, N - 1);
            float4 v = __ldg(&((const float4*)g_agg)[((size_t)nm * TT + t) * 4 + q]);
            a[m][0] = v.x; a[m][1] = v.y; a[m][2] = v.z; a[m][3] = v.w;
        }
        float p = sp[t];
        u64 t2[4][4];

        // ---- r gate: R = sigmoid(r) * H ----
        float R[4][8];
        gate4(t2, sA[1], sB[1], sc[1], a, H, q2, lanebase);
        #pragma unroll
        for (int m = 0; m < 4; m++)
            #pragma unroll
            for (int pp = 0; pp < 4; pp++) {
                float x0, x1;
                up2(t2[m][pp], x0, x1);
                R[m][2 * pp]     = sigf(x0) * H[m][2 * pp];
                R[m][2 * pp + 1] = sigf(x1) * H[m][2 * pp + 1];
            }

        // ---- candidate: HT = tanh(h(R)) ----
        float HT[4][8];
        gate4(t2, sA[2], sB[2], sc[2], a, R, q2, lanebase);
        #pragma unroll
        for (int m = 0; m < 4; m++)
            #pragma unroll
            for (int pp = 0; pp < 4; pp++) {
                float x0, x1;
                up2(t2[m][pp], x0, x1);
                HT[m][2 * pp]     = tanhfast(x0);
                HT[m][2 * pp + 1] = tanhfast(x1);
            }

        // ---- z gate + state update ----
        gate4(t2, sA[0], sB[0], sc[0], a, H, q2, lanebase);
        #pragma unroll
        for (int m = 0; m < 4; m++)
            #pragma unroll
            for (int pp = 0; pp < 4; pp++) {
                float x0, x1;
                up2(t2[m][pp], x0, x1);
                int j = 2 * pp;
                float z0 = sigf(x0), z1 = sigf(x1);
                H[m][j]     = z0 * H[m][j]     + (1.0f - z0) * HT[m][j];
                H[m][j + 1] = z1 * H[m][j + 1] + (1.0f - z1) * HT[m][j + 1];
                acc[m][j]     = fmaf(p, H[m][j],     acc[m][j]);
                acc[m][j + 1] = fmaf(p, H[m][j + 1], acc[m][j + 1]);
            }
    }

    // ---- relu + reduce: per-column sums across the 4 nodes, then across
    // the 8 same-q lanes of the warp, then block, then global ----
    #pragma unroll
    for (int j = 0; j < 8; j++) {
        float s = 0.0f;
        #pragma unroll
        for (int m = 0; m < 4; m++) {
            if (base + m < N) {
                float v = acc[m][j];
                s += v > 0.0f ? v : 0.0f;
            }
        }
        s += __shfl_xor_sync(0xffffffffu, s, 4);
        s += __shfl_xor_sync(0xffffffffu, s, 8);
        s += __shfl_xor_sync(0xffffffffu, s, 16);
        if ((tid & 31) < 4) atomicAdd(&bsum[q * 8 + j], s);
    }
    __syncthreads();
    if (tid < HID) atomicAdd(&g_hsum[tid], bsum[tid]);
}

// Final readout; also re-zeros g_hsum for the next replay.
__global__ void k_final(const float* __restrict__ linW, const float* __restrict__ linb,
                        float* out, int N) {
    int j = threadIdx.x;   // 32 threads
    float invN = 1.0f / (float)N;
    float h = g_hsum[j];
    g_hsum[j] = 0.0f;
    float v = h * invN * linW[j];
    #pragma unroll
    for (int o = 16; o; o >>= 1) v += __shfl_xor_sync(0xffffffffu, v, o);
    if (j == 0) {
        float r = v + linb[0];
        out[0] = r > 0.0f ? r : 0.0f;
    }
}

// ---------------- launcher ----------------
extern "C" void kernel_launch(void* const* d_in, const int* in_sizes, int n_in,
                              void* d_out, int out_size) {
    const float* x    = (const float*)d_in[0];
    const int*   ei   = (const int*)  d_in[1];
    const float* att  = (const float*)d_in[2];
    const float* Wz   = (const float*)d_in[3];
    const float* bz   = (const float*)d_in[4];
    const float* Wr   = (const float*)d_in[5];
    const float* br   = (const float*)d_in[6];
    const float* Wh   = (const float*)d_in[7];
    const float* bh   = (const float*)d_in[8];
    const float* LzW  = (const float*)d_in[9];
    const float* Lzb  = (const float*)d_in[10];
    const float* LrW  = (const float*)d_in[11];
    const float* Lrb  = (const float*)d_in[12];
    const float* LhW  = (const float*)d_in[13];
    const float* Lhb  = (const float*)d_in[14];
    const float* linW = (const float*)d_in[15];
    const float* linb = (const float*)d_in[16];

    int N = in_sizes[0] / FT;
    int E = in_sizes[1] / 2;
    int NB = (N + SB - 1) / SB;
    int NG = (N + 3) / 4;               // gru groups (4 nodes each)

    k_cnt<<<(E + 255) / 256, 256>>>(ei, E);
    k_half<<<(N + 3) / 4, 256>>>(x, N);
    k_prep<<<1, 512>>>(Wz, bz, Wr, br, Wh, bh, LzW, Lzb, LrW, Lrb, LhW, Lhb, att);
    k_scan_a<<<NB, SB>>>(N);
    k_scan_b<<<1, 128>>>(NB, N, E);
    k_scan_c<<<NB, SB>>>(N);
    k_fill<<<(E + 255) / 256, 256>>>(ei, E, N);
    k_gather<<<(N * 32 + 255) / 256, 256>>>(N);
    k_gru<<<(NG * 4 + 127) / 128, 128>>>(LzW, LrW, LhW, N);
    k_final<<<1, 32>>>(linW, linb, (float*)d_out, N);
}

// round 10
// speedup vs baseline: 3.6487x; 1.7637x over previous
#include <cuda_runtime.h>
#include <cuda_fp16.h>
#include <math.h>

#define NMAX 50000
#define EMAX 1600000
#define FIN 16
#define TT 12
#define HID 32
#define FT (FIN*TT)   // 192 values per node
#define SB 512        // scan block size

// ---------------- scratch (static device globals; no allocation) ----------------
__device__ int    g_cnt[NMAX];                    // in-degree counts; zeroed by k_fill each run
__device__ int    g_rowptr[NMAX + 1];             // CSR row pointers
__device__ int    g_cur[NMAX];                    // fill cursors
__device__ int2   g_sw[EMAX];                     // CSR payload: {src, bits(norm weight)}
__device__ int    g_part[256];                    // scan partials
__device__ float  g_dis[NMAX];                    // rsqrt(degree incl. self-loop)
__device__ __half g_xh[(size_t)NMAX * FT];        // fp16 features, t-major [N][T][F]
__device__ __half g_aggh[(size_t)NMAX * FT];      // aggregated features fp16, t-major [N][T][F]
__device__ float  g_A[3 * FIN * HID];             // folded W_g @ L_g_top
__device__ float  g_c[3 * HID];                   // folded biases
__device__ float  g_probs[TT];                    // softmax(att)
__device__ float  g_hsum[HID];                    // sum over nodes of relu(Hacc); zeroed by k_final

// ---------------- helpers ----------------
__device__ __forceinline__ float sigf(float x) {
    return __fdividef(1.0f, 1.0f + __expf(-x));
}
__device__ __forceinline__ float tanhfast(float x) {
    return fmaf(2.0f, __fdividef(1.0f, 1.0f + __expf(-2.0f * x)), -1.0f);
}
union F4H2 { float4 f4; __half2 h2[4]; };

__device__ __forceinline__ unsigned h2pack(float lo, float hi) {
    __half2 h = __floats2half2_rn(lo, hi);
    return *reinterpret_cast<unsigned*>(&h);
}

// m16n8k16 row.col f16 inputs, f32 accum (C += A*B)
__device__ __forceinline__ void mma16816(float* c, const unsigned* a, const unsigned* b) {
    asm volatile(
        "mma.sync.aligned.m16n8k16.row.col.f32.f16.f16.f32 "
        "{%0,%1,%2,%3}, {%4,%5,%6,%7}, {%8,%9}, {%0,%1,%2,%3};"
        : "+f"(c[0]), "+f"(c[1]), "+f"(c[2]), "+f"(c[3])
        : "r"(a[0]), "r"(a[1]), "r"(a[2]), "r"(a[3]), "r"(b[0]), "r"(b[1]));
}

// ---------------- kernels ----------------
__global__ void k_cnt(const int* __restrict__ ei, int E) {
    int e = blockIdx.x * blockDim.x + threadIdx.x;
    if (e < E) atomicAdd(&g_cnt[ei[E + e]], 1);
}

// Convert x [N][F][T] fp32 -> g_xh [N][T][F] fp16. 4 nodes per block of 256.
// Shift/and-only indexing in the hot write phase.
__global__ void k_half(const float* __restrict__ x, int N) {
    __shared__ float sx[4 * FT];
    int tid = threadIdx.x;
    size_t base = (size_t)blockIdx.x * 4 * FT;
    size_t lim  = (size_t)N * FT;
    // load 4*192 floats as 192 float4 (x rows are 16B aligned)
    const float4* x4 = (const float4*)(x + base);
    int nvalid = (int)min((size_t)(4 * FT), lim - base);
    #pragma unroll
    for (int i = tid; i < FT; i += 256) {       // 192 float4s
        if (i * 4 < nvalid) ((float4*)sx)[i] = x4[i];
    }
    __syncthreads();
    int nn = tid >> 6, u = tid & 63;
    int node = blockIdx.x * 4 + nn;
    if (node < N) {
        const float* s = sx + nn * FT;
        __half* d = g_xh + (size_t)node * FT;
        #pragma unroll
        for (int r = 0; r < 3; r++) {
            int o = (r << 6) + u;               // output index (t-major)
            int t = o >> 4, f = o & 15;
            d[o] = __float2half(s[f * TT + t]);
        }
    }
}

// Precompute folded matrices/biases + softmax(att). One block of 512 threads.
__global__ void k_prep(const float* __restrict__ Wz, const float* __restrict__ bz,
                       const float* __restrict__ Wr, const float* __restrict__ br,
                       const float* __restrict__ Wh, const float* __restrict__ bh,
                       const float* __restrict__ LzW, const float* __restrict__ Lzb,
                       const float* __restrict__ LrW, const float* __restrict__ Lrb,
                       const float* __restrict__ LhW, const float* __restrict__ Lhb,
                       const float* __restrict__ att) {
    int id = threadIdx.x;                       // 512 threads
    const float* W[3]  = {Wz, Wr, Wh};
    const float* L[3]  = {LzW, LrW, LhW};
    const float* bb[3] = {bz, br, bh};
    const float* Lb[3] = {Lzb, Lrb, Lhb};

    int f = id >> 5, j = id & 31;               // 16 x 32 = 512
    #pragma unroll
    for (int g = 0; g < 3; g++) {
        float s = 0.0f;
        #pragma unroll
        for (int k = 0; k < HID; k++)
            s = fmaf(__ldg(&W[g][f * HID + k]), __ldg(&L[g][k * HID + j]), s);
        g_A[(g * FIN + f) * HID + j] = s;
    }
    if (id < 3 * HID) {
        int g = id >> 5, jj = id & 31;
        float s = __ldg(&Lb[g][jj]);
        #pragma unroll
        for (int k = 0; k < HID; k++)
            s = fmaf(__ldg(&bb[g][k]), __ldg(&L[g][k * HID + jj]), s);
        g_c[g * HID + jj] = s;
    }
    if (id < 32) {
        float v = (id < TT) ? __ldg(&att[id]) : -1e30f;
        float m = v;
        #pragma unroll
        for (int o = 16; o; o >>= 1) m = fmaxf(m, __shfl_xor_sync(0xffffffffu, m, o));
        float e = (id < TT) ? __expf(v - m) : 0.0f;
        float s = e;
        #pragma unroll
        for (int o = 16; o; o >>= 1) s += __shfl_xor_sync(0xffffffffu, s, o);
        if (id < TT) g_probs[id] = e * __fdividef(1.0f, s);
    }
}

// ---- parallel 3-phase scan ----
__global__ void k_scan_a(int N) {
    __shared__ int ws[SB / 32];
    int tid = threadIdx.x;
    int i = blockIdx.x * SB + tid;
    int v = (i < N) ? g_cnt[i] : 0;
    #pragma unroll
    for (int o = 16; o; o >>= 1) v += __shfl_xor_sync(0xffffffffu, v, o);
    if ((tid & 31) == 0) ws[tid >> 5] = v;
    __syncthreads();
    if (tid < SB / 32) {
        int w = ws[tid];
        #pragma unroll
        for (int o = 8; o; o >>= 1) w += __shfl_xor_sync(0xffffu, w, o);
        if (tid == 0) g_part[blockIdx.x] = w;
    }
}

__global__ void k_scan_b(int NB, int N, int E) {
    __shared__ int ws[4];
    int tid = threadIdx.x, lane = tid & 31, wid = tid >> 5;
    int orig = (tid < NB) ? g_part[tid] : 0;
    int v = orig;
    #pragma unroll
    for (int o = 1; o < 32; o <<= 1) {
        int t = __shfl_up_sync(0xffffffffu, v, o);
        if (lane >= o) v += t;
    }
    if (lane == 31) ws[wid] = v;
    __syncthreads();
    if (wid == 0 && lane < 4) {
        int w = ws[lane];
        #pragma unroll
        for (int o = 1; o < 4; o <<= 1) {
            int t = __shfl_up_sync(0xfu, w, o);
            if (lane >= o) w += t;
        }
        ws[lane] = w;
    }
    __syncthreads();
    int incl = v + (wid > 0 ? ws[wid - 1] : 0);
    if (tid < NB) g_part[tid] = incl - orig;     // exclusive
    if (tid == 0) g_rowptr[N] = E;
}

__global__ void k_scan_c(int N) {
    __shared__ int ws[SB / 32];
    int tid = threadIdx.x, lane = tid & 31, wid = tid >> 5;
    int i = blockIdx.x * SB + tid;
    int c = (i < N) ? g_cnt[i] : 0;
    int v = c;
    #pragma unroll
    for (int o = 1; o < 32; o <<= 1) {
        int t = __shfl_up_sync(0xffffffffu, v, o);
        if (lane >= o) v += t;
    }
    if (lane == 31) ws[wid] = v;
    __syncthreads();
    if (wid == 0 && lane < SB / 32) {
        int w = ws[lane];
        #pragma unroll
        for (int o = 1; o < SB / 32; o <<= 1) {
            int t = __shfl_up_sync((1u << (SB / 32)) - 1u, w, o);
            if (lane >= o) w += t;
        }
        ws[lane] = w;
    }
    __syncthreads();
    int excl = v - c + (wid > 0 ? ws[wid - 1] : 0) + g_part[blockIdx.x];
    if (i < N) {
        g_rowptr[i] = excl;
        g_cur[i]    = excl;
        g_dis[i]    = rsqrtf((float)(c + 1));    // +1 self-loop
    }
}

// CSR fill; also re-zeros g_cnt for the next replay.
__global__ void k_fill(const int* __restrict__ ei, int E, int N) {
    int e = blockIdx.x * blockDim.x + threadIdx.x;
    if (e < N) g_cnt[e] = 0;
    if (e >= E) return;
    int s = ei[e];
    int d = ei[E + e];
    int p = atomicAdd(&g_cur[d], 1);
    g_sw[p] = make_int2(s, __float_as_int(g_dis[s] * g_dis[d]));
}

// Warp-per-node gather on fp16 features (fp32 accumulation, fp16 output).
__global__ void __launch_bounds__(256)
k_gather(int N) {
    __shared__ int2 stage[8][32];
    int gw   = (blockIdx.x * blockDim.x + threadIdx.x) >> 5;
    int wloc = threadIdx.x >> 5;
    int lane = threadIdx.x & 31;
    if (gw >= N) return;
    int n = gw;

    int beg = g_rowptr[n];
    int end = g_rowptr[n + 1];
    float dd = g_dis[n];
    int ln = (lane < 24) ? lane : 0;        // clamped payload lane

    float acc[8];
    {
        float inv = dd * dd;                       // 1/deg (self-loop term)
        F4H2 v; v.f4 = ((const float4*)(g_xh + (size_t)n * FT))[ln];
        #pragma unroll
        for (int q = 0; q < 4; q++) {
            float2 f = __half22float2(v.h2[q]);
            acc[2 * q]     = inv * f.x;
            acc[2 * q + 1] = inv * f.y;
        }
    }

    for (int i = beg; i < end; i += 32) {
        int j = i + lane;
        if (j < end) stage[wloc][lane] = g_sw[j];
        __syncwarp();
        int m = min(32, end - i);
        #pragma unroll 8
        for (int u = 0; u < m; u++) {
            int2 sw = stage[wloc][u];
            float ww = __int_as_float(sw.y);
            F4H2 v; v.f4 = ((const float4*)(g_xh + (size_t)sw.x * FT))[ln];
            #pragma unroll
            for (int q = 0; q < 4; q++) {
                float2 f = __half22float2(v.h2[q]);
                acc[2 * q]     = fmaf(ww, f.x, acc[2 * q]);
                acc[2 * q + 1] = fmaf(ww, f.y, acc[2 * q + 1]);
            }
        }
        __syncwarp();
    }

    if (lane < 24) {
        F4H2 st;
        #pragma unroll
        for (int q = 0; q < 4; q++)
            st.h2[q] = __floats2half2_rn(acc[2 * q], acc[2 * q + 1]);
        ((float4*)(g_aggh + (size_t)n * FT))[lane] = st.f4;
    }
}

// ---- tensor-core GRU: warp handles 16 nodes via m16n8k16 HMMA ----
// Per timestep: Czr[16x64] = [a(16) H(32)] @ Wzr[48x64]  (cols 0-31 = z, 32-63 = r)
//               Ch [16x32] = [a(16) R(32)] @ Wh [48x32]
// C(m16n8) fragments pack directly into A(m16k16) fragments (same lane layout),
// so the recurrent handoff is a pure register f32->f16x2 pack.
__device__ __forceinline__ float wzr_at(int k, int n,
                                        const float* LzW, const float* LrW) {
    int g = n >> 5, col = n & 31;
    if (k < 16) return g_A[(g * 16 + k) * 32 + col];
    const float* L = g ? LrW : LzW;
    return L[(k + 16) * 32 + col];          // bottom rows 32..63 of L
}
__device__ __forceinline__ float wh_at(int k, int n, const float* LhW) {
    if (k < 16) return g_A[(2 * 16 + k) * 32 + n];
    return LhW[(k + 16) * 32 + n];
}

__global__ void __launch_bounds__(128)
k_gru(const float* __restrict__ LzW, const float* __restrict__ LrW,
      const float* __restrict__ LhW, int N) {
    __shared__ float sp[TT];
    __shared__ float bsum[HID];

    int tid = threadIdx.x;
    if (tid < TT) sp[tid] = g_probs[tid];
    if (tid < HID) bsum[tid] = 0.0f;
    __syncthreads();

    int lane = tid & 31;
    int w = blockIdx.x * 4 + (tid >> 5);
    int NW = (N + 15) / 16;
    if (w < NW) {
        int base = w * 16;
        int qr = lane >> 2;         // row 0..7 (also n within 8-col tile for B)
        int qc = lane & 3;          // col-pair 0..3

        // ---- weight B-fragments (once) ----
        unsigned bzr[3][8][2];      // k-tile s, n-tile j
        unsigned bh[3][4][2];
        #pragma unroll
        for (int s = 0; s < 3; s++) {
            int k0 = 16 * s + 2 * qc;
            #pragma unroll
            for (int j = 0; j < 8; j++) {
                int n = 8 * j + qr;
                bzr[s][j][0] = h2pack(wzr_at(k0,     n, LzW, LrW), wzr_at(k0 + 1, n, LzW, LrW));
                bzr[s][j][1] = h2pack(wzr_at(k0 + 8, n, LzW, LrW), wzr_at(k0 + 9, n, LzW, LrW));
            }
            #pragma unroll
            for (int j = 0; j < 4; j++) {
                int n = 8 * j + qr;
                bh[s][j][0] = h2pack(wh_at(k0,     n, LhW), wh_at(k0 + 1, n, LhW));
                bh[s][j][1] = h2pack(wh_at(k0 + 8, n, LhW), wh_at(k0 + 9, n, LhW));
            }
        }
        // ---- bias fragments (c0,c1; rows share cols so c2=c0, c3=c1) ----
        float bzc[8][2], bhc[4][2];
        #pragma unroll
        for (int j = 0; j < 8; j++) {
            int n = 8 * j + 2 * qc;
            bzc[j][0] = g_c[n]; bzc[j][1] = g_c[n + 1];
        }
        #pragma unroll
        for (int j = 0; j < 4; j++) {
            int n = 8 * j + 2 * qc;
            bhc[j][0] = g_c[64 + n]; bhc[j][1] = g_c[64 + n + 1];
        }

        // a-operand pointers (u32 view of fp16 agg rows for rows qr, qr+8)
        int n0 = min(base + qr,     N - 1);
        int n1 = min(base + qr + 8, N - 1);
        const unsigned* A0 = (const unsigned*)(g_aggh + (size_t)n0 * FT) + qc;
        const unsigned* A1 = (const unsigned*)(g_aggh + (size_t)n1 * FT) + qc;

        float H[4][4], acc[4][4];
        #pragma unroll
        for (int j = 0; j < 4; j++)
            #pragma unroll
            for (int i = 0; i < 4; i++) { H[j][i] = 0.0f; acc[j][i] = 0.0f; }

        #pragma unroll 1
        for (int t = 0; t < TT; t++) {
            float p = sp[t];
            unsigned af[4];
            af[0] = A0[t * 8];     af[1] = A1[t * 8];
            af[2] = A0[t * 8 + 4]; af[3] = A1[t * 8 + 4];

            // H -> A fragments (k-tiles 1,2)
            unsigned hA1[4] = { h2pack(H[0][0], H[0][1]), h2pack(H[0][2], H[0][3]),
                                h2pack(H[1][0], H[1][1]), h2pack(H[1][2], H[1][3]) };
            unsigned hA2[4] = { h2pack(H[2][0], H[2][1]), h2pack(H[2][2], H[2][3]),
                                h2pack(H[3][0], H[3][1]), h2pack(H[3][2], H[3][3]) };

            // ---- z,r GEMM ----
            float Czr[8][4];
            #pragma unroll
            for (int j = 0; j < 8; j++) {
                Czr[j][0] = bzc[j][0]; Czr[j][1] = bzc[j][1];
                Czr[j][2] = bzc[j][0]; Czr[j][3] = bzc[j][1];
            }
            #pragma unroll
            for (int j = 0; j < 8; j++) {
                mma16816(Czr[j], af,  bzr[0][j]);
                mma16816(Czr[j], hA1, bzr[1][j]);
                mma16816(Czr[j], hA2, bzr[2][j]);
            }
            float Z[4][4], R[4][4];
            #pragma unroll
            for (int j = 0; j < 4; j++)
                #pragma unroll
                for (int i = 0; i < 4; i++) {
                    Z[j][i] = sigf(Czr[j][i]);
                    R[j][i] = sigf(Czr[4 + j][i]) * H[j][i];
                }

            // ---- candidate GEMM ----
            unsigned rA1[4] = { h2pack(R[0][0], R[0][1]), h2pack(R[0][2], R[0][3]),
                                h2pack(R[1][0], R[1][1]), h2pack(R[1][2], R[1][3]) };
            unsigned rA2[4] = { h2pack(R[2][0], R[2][1]), h2pack(R[2][2], R[2][3]),
                                h2pack(R[3][0], R[3][1]), h2pack(R[3][2], R[3][3]) };
            float Ch[4][4];
            #pragma unroll
            for (int j = 0; j < 4; j++) {
                Ch[j][0] = bhc[j][0]; Ch[j][1] = bhc[j][1];
                Ch[j][2] = bhc[j][0]; Ch[j][3] = bhc[j][1];
            }
            #pragma unroll
            for (int j = 0; j < 4; j++) {
                mma16816(Ch[j], af,  bh[0][j]);
                mma16816(Ch[j], rA1, bh[1][j]);
                mma16816(Ch[j], rA2, bh[2][j]);
            }
            // ---- state update ----
            #pragma unroll
            for (int j = 0; j < 4; j++)
                #pragma unroll
                for (int i = 0; i < 4; i++) {
                    float ht = tanhfast(Ch[j][i]);
                    float z = Z[j][i];
                    H[j][i] = z * H[j][i] + (1.0f - z) * ht;
                    acc[j][i] = fmaf(p, H[j][i], acc[j][i]);
                }
        }

        // ---- relu + reduce: rows -> columns ----
        bool v0 = (base + qr)     < N;
        bool v1 = (base + qr + 8) < N;
        #pragma unroll
        for (int j = 0; j < 4; j++) {
            float a0 = acc[j][0], a1 = acc[j][1], a2 = acc[j][2], a3 = acc[j][3];
            float s0 = (v0 ? fmaxf(a0, 0.0f) : 0.0f) + (v1 ? fmaxf(a2, 0.0f) : 0.0f);
            float s1 = (v0 ? fmaxf(a1, 0.0f) : 0.0f) + (v1 ? fmaxf(a3, 0.0f) : 0.0f);
            #pragma unroll
            for (int o = 4; o < 32; o <<= 1) {
                s0 += __shfl_xor_sync(0xffffffffu, s0, o);
                s1 += __shfl_xor_sync(0xffffffffu, s1, o);
            }
            if (qr == 0) {
                atomicAdd(&bsum[8 * j + 2 * qc],     s0);
                atomicAdd(&bsum[8 * j + 2 * qc + 1], s1);
            }
        }
    }
    __syncthreads();
    if (tid < HID) atomicAdd(&g_hsum[tid], bsum[tid]);
}

// Final readout; also re-zeros g_hsum for the next replay.
__global__ void k_final(const float* __restrict__ linW, const float* __restrict__ linb,
                        float* out, int N) {
    int j = threadIdx.x;   // 32 threads
    float invN = 1.0f / (float)N;
    float h = g_hsum[j];
    g_hsum[j] = 0.0f;
    float v = h * invN * linW[j];
    #pragma unroll
    for (int o = 16; o; o >>= 1) v += __shfl_xor_sync(0xffffffffu, v, o);
    if (j == 0) {
        float r = v + linb[0];
        out[0] = r > 0.0f ? r : 0.0f;
    }
}

// ---------------- launcher ----------------
extern "C" void kernel_launch(void* const* d_in, const int* in_sizes, int n_in,
                              void* d_out, int out_size) {
    const float* x    = (const float*)d_in[0];
    const int*   ei   = (const int*)  d_in[1];
    const float* att  = (const float*)d_in[2];
    const float* Wz   = (const float*)d_in[3];
    const float* bz   = (const float*)d_in[4];
    const float* Wr   = (const float*)d_in[5];
    const float* br   = (const float*)d_in[6];
    const float* Wh   = (const float*)d_in[7];
    const float* bh   = (const float*)d_in[8];
    const float* LzW  = (const float*)d_in[9];
    const float* Lzb  = (const float*)d_in[10];
    const float* LrW  = (const float*)d_in[11];
    const float* Lrb  = (const float*)d_in[12];
    const float* LhW  = (const float*)d_in[13];
    const float* Lhb  = (const float*)d_in[14];
    const float* linW = (const float*)d_in[15];
    const float* linb = (const float*)d_in[16];

    int N = in_sizes[0] / FT;
    int E = in_sizes[1] / 2;
    int NB = (N + SB - 1) / SB;
    int NW = (N + 15) / 16;             // gru warps (16 nodes each)

    k_cnt<<<(E + 255) / 256, 256>>>(ei, E);
    k_half<<<(N + 3) / 4, 256>>>(x, N);
    k_prep<<<1, 512>>>(Wz, bz, Wr, br, Wh, bh, LzW, Lzb, LrW, Lrb, LhW, Lhb, att);
    k_scan_a<<<NB, SB>>>(N);
    k_scan_b<<<1, 128>>>(NB, N, E);
    k_scan_c<<<NB, SB>>>(N);
    k_fill<<<(E + 255) / 256, 256>>>(ei, E, N);
    k_gather<<<(N * 32 + 255) / 256, 256>>>(N);
    k_gru<<<(NW + 3) / 4, 128>>>(LzW, LrW, LhW, N);
    k_final<<<1, 32>>>(linW, linb, (float*)d_out, N);
}

// round 11
// speedup vs baseline: 3.9894x; 1.0934x over previous
#include <cuda_runtime.h>
#include <cuda_fp16.h>
#include <math.h>

#define NMAX 50000
#define EMAX 1600000
#define FIN 16
#define TT 12
#define HID 32
#define FT (FIN*TT)   // 192 values per node
#define SB 512        // scan block size

// ---------------- scratch (static device globals; no allocation) ----------------
__device__ int    g_cnt[NMAX];                    // in-degree counts; zeroed by k_fill each run
__device__ int    g_rowptr[NMAX + 1];             // CSR row pointers
__device__ int    g_cur[NMAX];                    // fill cursors
__device__ int2   g_sw[EMAX];                     // CSR payload: {src, bits(norm weight)}
__device__ int    g_part[256];                    // scan partials
__device__ float  g_dis[NMAX];                    // rsqrt(degree incl. self-loop)
__device__ __half g_xh[(size_t)NMAX * FT];        // fp16 features, t-major [N][T][F]
__device__ __half g_aggh[(size_t)NMAX * FT];      // aggregated features fp16, t-major [N][T][F]
__device__ float  g_A[3 * FIN * HID];             // folded W_g @ L_g_top
__device__ float  g_c[3 * HID];                   // folded biases
__device__ float  g_probs[TT];                    // softmax(att)
__device__ float  g_hsum[HID];                    // sum over nodes of relu(Hacc); zeroed by k_final

// ---------------- helpers ----------------
__device__ __forceinline__ float sigf(float x) {
    return __fdividef(1.0f, 1.0f + __expf(-x));
}
__device__ __forceinline__ float tanhfast(float x) {
    return fmaf(2.0f, __fdividef(1.0f, 1.0f + __expf(-2.0f * x)), -1.0f);
}
union F4H2 { float4 f4; __half2 h2[4]; };

typedef unsigned long long u64;
__device__ __forceinline__ u64 pk2(float x, float y) {
    u64 r; asm("mov.b64 %0, {%1,%2};" : "=l"(r) : "f"(x), "f"(y)); return r;
}
__device__ __forceinline__ u64 fma2(u64 a, u64 b, u64 c) {
    u64 d; asm("fma.rn.f32x2 %0, %1, %2, %3;" : "=l"(d) : "l"(a), "l"(b), "l"(c)); return d;
}
__device__ __forceinline__ void up2(u64 v, float& x, float& y) {
    asm("mov.b64 {%0,%1}, %2;" : "=f"(x), "=f"(y) : "l"(v));
}

__device__ __forceinline__ unsigned h2pack(float lo, float hi) {
    __half2 h = __floats2half2_rn(lo, hi);
    return *reinterpret_cast<unsigned*>(&h);
}

// m16n8k16 row.col f16 inputs, f32 accum (C += A*B)
__device__ __forceinline__ void mma16816(float* c, const unsigned* a, const unsigned* b) {
    asm volatile(
        "mma.sync.aligned.m16n8k16.row.col.f32.f16.f16.f32 "
        "{%0,%1,%2,%3}, {%4,%5,%6,%7}, {%8,%9}, {%0,%1,%2,%3};"
        : "+f"(c[0]), "+f"(c[1]), "+f"(c[2]), "+f"(c[3])
        : "r"(a[0]), "r"(a[1]), "r"(a[2]), "r"(a[3]), "r"(b[0]), "r"(b[1]));
}

// =======================================================================
// k_pre: fp16 transpose of x + edge-count red.add + weight fold/softmax
// grid = (N+3)/4 = 12500 blocks of 256 (3.2M threads >= E)
// =======================================================================
__global__ void __launch_bounds__(256)
k_pre(const float* __restrict__ x, const int* __restrict__ ei,
      const float* __restrict__ Wz, const float* __restrict__ bz,
      const float* __restrict__ Wr, const float* __restrict__ br,
      const float* __restrict__ Wh, const float* __restrict__ bh,
      const float* __restrict__ LzW, const float* __restrict__ Lzb,
      const float* __restrict__ LrW, const float* __restrict__ Lrb,
      const float* __restrict__ LhW, const float* __restrict__ Lhb,
      const float* __restrict__ att, int N, int E) {
    __shared__ float sx[4 * FT];
    int tid = threadIdx.x;

    // --- edge-count (fire-and-forget reduction, no return) ---
    int gt = blockIdx.x * 256 + tid;
    if (gt < E) {
        int d = __ldg(&ei[E + gt]);
        asm volatile("red.global.add.s32 [%0], %1;" :: "l"(&g_cnt[d]), "r"(1) : "memory");
    }

    // --- conversion: 4 nodes per block, [N][F][T] f32 -> [N][T][F] f16 ---
    size_t base = (size_t)blockIdx.x * 4 * FT;
    size_t lim  = (size_t)N * FT;
    const float4* x4 = (const float4*)(x + base);
    int nvalid = (int)min((size_t)(4 * FT), lim - base);
    #pragma unroll
    for (int i = tid; i < FT; i += 256) {       // 192 float4s
        if (i * 4 < nvalid) ((float4*)sx)[i] = x4[i];
    }
    __syncthreads();
    {
        int nn = tid >> 6, u = tid & 63;
        int node = blockIdx.x * 4 + nn;
        if (node < N) {
            const float* s = sx + nn * FT;
            __half* d = g_xh + (size_t)node * FT;
            #pragma unroll
            for (int r = 0; r < 3; r++) {
                int o = (r << 6) + u;           // output index (t-major)
                int t = o >> 4, f = o & 15;
                d[o] = __float2half(s[f * TT + t]);
            }
        }
    }

    // --- weight fold: block g in {0,1,2} handles gate g ---
    if (blockIdx.x < 3) {
        int g = blockIdx.x;
        const float* W  = (g == 0) ? Wz : (g == 1) ? Wr : Wh;
        const float* L  = (g == 0) ? LzW : (g == 1) ? LrW : LhW;
        const float* bb = (g == 0) ? bz : (g == 1) ? br : bh;
        const float* Lb = (g == 0) ? Lzb : (g == 1) ? Lrb : Lhb;
        #pragma unroll
        for (int rep = 0; rep < 2; rep++) {
            int id = tid + rep * 256;           // 512 (f,j) pairs
            int f = id >> 5, j = id & 31;
            float s = 0.0f;
            #pragma unroll
            for (int k = 0; k < HID; k++)
                s = fmaf(__ldg(&W[f * HID + k]), __ldg(&L[k * HID + j]), s);
            g_A[(g * FIN + f) * HID + j] = s;
        }
        if (tid < HID) {
            float s = __ldg(&Lb[tid]);
            #pragma unroll
            for (int k = 0; k < HID; k++)
                s = fmaf(__ldg(&bb[k]), __ldg(&L[k * HID + tid]), s);
            g_c[g * HID + tid] = s;
        }
        if (g == 0 && tid >= 32 && tid < 64) {  // softmax on warp 1
            int l = tid & 31;
            float v = (l < TT) ? __ldg(&att[l]) : -1e30f;
            float m = v;
            #pragma unroll
            for (int o = 16; o; o >>= 1) m = fmaxf(m, __shfl_xor_sync(0xffffffffu, m, o));
            float e = (l < TT) ? __expf(v - m) : 0.0f;
            float s = e;
            #pragma unroll
            for (int o = 16; o; o >>= 1) s += __shfl_xor_sync(0xffffffffu, s, o);
            if (l < TT) g_probs[l] = e * __fdividef(1.0f, s);
        }
    }
}

// ---- parallel 3-phase scan ----
__global__ void k_scan_a(int N) {
    __shared__ int ws[SB / 32];
    int tid = threadIdx.x;
    int i = blockIdx.x * SB + tid;
    int v = (i < N) ? g_cnt[i] : 0;
    #pragma unroll
    for (int o = 16; o; o >>= 1) v += __shfl_xor_sync(0xffffffffu, v, o);
    if ((tid & 31) == 0) ws[tid >> 5] = v;
    __syncthreads();
    if (tid < SB / 32) {
        int w = ws[tid];
        #pragma unroll
        for (int o = 8; o; o >>= 1) w += __shfl_xor_sync(0xffffu, w, o);
        if (tid == 0) g_part[blockIdx.x] = w;
    }
}

__global__ void k_scan_b(int NB, int N, int E) {
    __shared__ int ws[4];
    int tid = threadIdx.x, lane = tid & 31, wid = tid >> 5;
    int orig = (tid < NB) ? g_part[tid] : 0;
    int v = orig;
    #pragma unroll
    for (int o = 1; o < 32; o <<= 1) {
        int t = __shfl_up_sync(0xffffffffu, v, o);
        if (lane >= o) v += t;
    }
    if (lane == 31) ws[wid] = v;
    __syncthreads();
    if (wid == 0 && lane < 4) {
        int w = ws[lane];
        #pragma unroll
        for (int o = 1; o < 4; o <<= 1) {
            int t = __shfl_up_sync(0xfu, w, o);
            if (lane >= o) w += t;
        }
        ws[lane] = w;
    }
    __syncthreads();
    int incl = v + (wid > 0 ? ws[wid - 1] : 0);
    if (tid < NB) g_part[tid] = incl - orig;     // exclusive
    if (tid == 0) g_rowptr[N] = E;
}

__global__ void k_scan_c(int N) {
    __shared__ int ws[SB / 32];
    int tid = threadIdx.x, lane = tid & 31, wid = tid >> 5;
    int i = blockIdx.x * SB + tid;
    int c = (i < N) ? g_cnt[i] : 0;
    int v = c;
    #pragma unroll
    for (int o = 1; o < 32; o <<= 1) {
        int t = __shfl_up_sync(0xffffffffu, v, o);
        if (lane >= o) v += t;
    }
    if (lane == 31) ws[wid] = v;
    __syncthreads();
    if (wid == 0 && lane < SB / 32) {
        int w = ws[lane];
        #pragma unroll
        for (int o = 1; o < SB / 32; o <<= 1) {
            int t = __shfl_up_sync((1u << (SB / 32)) - 1u, w, o);
            if (lane >= o) w += t;
        }
        ws[lane] = w;
    }
    __syncthreads();
    int excl = v - c + (wid > 0 ? ws[wid - 1] : 0) + g_part[blockIdx.x];
    if (i < N) {
        g_rowptr[i] = excl;
        g_cur[i]    = excl;
        g_dis[i]    = rsqrtf((float)(c + 1));    // +1 self-loop
    }
}

// CSR fill: 4 edges per thread (batched loads, higher MLP); re-zeros g_cnt.
__global__ void k_fill(const int* __restrict__ ei, int E, int N) {
    int i = blockIdx.x * blockDim.x + threadIdx.x;
    if (i < N) g_cnt[i] = 0;
    int base = i * 4;
    if (base >= E) return;
    int m = min(4, E - base);
    int s[4], d[4];
    float ws[4];
    #pragma unroll
    for (int u = 0; u < 4; u++) {
        if (u < m) {
            s[u] = __ldg(&ei[base + u]);
            d[u] = __ldg(&ei[E + base + u]);
        }
    }
    #pragma unroll
    for (int u = 0; u < 4; u++) {
        if (u < m) ws[u] = g_dis[s[u]] * g_dis[d[u]];
    }
    #pragma unroll
    for (int u = 0; u < 4; u++) {
        if (u < m) {
            int p = atomicAdd(&g_cur[d[u]], 1);
            g_sw[p] = make_int2(s[u], __float_as_int(ws[u]));
        }
    }
}

// Warp-per-node gather on fp16 features (packed f32x2 accumulation, fp16 out).
__global__ void __launch_bounds__(256)
k_gather(int N) {
    __shared__ int2 stage[8][32];
    int gw   = (blockIdx.x * blockDim.x + threadIdx.x) >> 5;
    int wloc = threadIdx.x >> 5;
    int lane = threadIdx.x & 31;
    if (gw >= N) return;
    int n = gw;

    int beg = g_rowptr[n];
    int end = g_rowptr[n + 1];
    float dd = g_dis[n];
    int ln = (lane < 24) ? lane : 0;        // clamped payload lane

    u64 acc2[4];
    {
        float inv = dd * dd;                       // 1/deg (self-loop term)
        u64 ip = pk2(inv, inv);
        F4H2 v; v.f4 = ((const float4*)(g_xh + (size_t)n * FT))[ln];
        #pragma unroll
        for (int q = 0; q < 4; q++) {
            float2 f = __half22float2(v.h2[q]);
            u64 fp = pk2(f.x, f.y);
            acc2[q] = fma2(ip, fp, pk2(0.0f, 0.0f));
        }
    }

    for (int i = beg; i < end; i += 32) {
        int j = i + lane;
        if (j < end) stage[wloc][lane] = g_sw[j];
        __syncwarp();
        int m = min(32, end - i);
        #pragma unroll 8
        for (int u = 0; u < m; u++) {
            int2 sw = stage[wloc][u];
            float ww = __int_as_float(sw.y);
            u64 wp = pk2(ww, ww);
            F4H2 v; v.f4 = ((const float4*)(g_xh + (size_t)sw.x * FT))[ln];
            #pragma unroll
            for (int q = 0; q < 4; q++) {
                float2 f = __half22float2(v.h2[q]);
                acc2[q] = fma2(wp, pk2(f.x, f.y), acc2[q]);
            }
        }
        __syncwarp();
    }

    if (lane < 24) {
        F4H2 st;
        #pragma unroll
        for (int q = 0; q < 4; q++) {
            float a0, a1;
            up2(acc2[q], a0, a1);
            st.h2[q] = __floats2half2_rn(a0, a1);
        }
        ((float4*)(g_aggh + (size_t)n * FT))[lane] = st.f4;
    }
}

// ---- tensor-core GRU: warp handles 16 nodes via m16n8k16 HMMA ----
__device__ __forceinline__ float wzr_at(int k, int n,
                                        const float* LzW, const float* LrW) {
    int g = n >> 5, col = n & 31;
    if (k < 16) return g_A[(g * 16 + k) * 32 + col];
    const float* L = g ? LrW : LzW;
    return L[(k + 16) * 32 + col];          // bottom rows 32..63 of L
}
__device__ __forceinline__ float wh_at(int k, int n, const float* LhW) {
    if (k < 16) return g_A[(2 * 16 + k) * 32 + n];
    return LhW[(k + 16) * 32 + n];
}

__global__ void __launch_bounds__(128)
k_gru(const float* __restrict__ LzW, const float* __restrict__ LrW,
      const float* __restrict__ LhW, int N) {
    __shared__ float sp[TT];
    __shared__ float bsum[HID];

    int tid = threadIdx.x;
    if (tid < TT) sp[tid] = g_probs[tid];
    if (tid < HID) bsum[tid] = 0.0f;
    __syncthreads();

    int lane = tid & 31;
    int w = blockIdx.x * 4 + (tid >> 5);
    int NW = (N + 15) / 16;
    if (w < NW) {
        int base = w * 16;
        int qr = lane >> 2;         // row 0..7 (also n within 8-col tile for B)
        int qc = lane & 3;          // col-pair 0..3

        // ---- weight B-fragments (once) ----
        unsigned bzr[3][8][2];      // k-tile s, n-tile j
        unsigned bh[3][4][2];
        #pragma unroll
        for (int s = 0; s < 3; s++) {
            int k0 = 16 * s + 2 * qc;
            #pragma unroll
            for (int j = 0; j < 8; j++) {
                int n = 8 * j + qr;
                bzr[s][j][0] = h2pack(wzr_at(k0,     n, LzW, LrW), wzr_at(k0 + 1, n, LzW, LrW));
                bzr[s][j][1] = h2pack(wzr_at(k0 + 8, n, LzW, LrW), wzr_at(k0 + 9, n, LzW, LrW));
            }
            #pragma unroll
            for (int j = 0; j < 4; j++) {
                int n = 8 * j + qr;
                bh[s][j][0] = h2pack(wh_at(k0,     n, LhW), wh_at(k0 + 1, n, LhW));
                bh[s][j][1] = h2pack(wh_at(k0 + 8, n, LhW), wh_at(k0 + 9, n, LhW));
            }
        }
        // ---- bias fragments ----
        float bzc[8][2], bhc[4][2];
        #pragma unroll
        for (int j = 0; j < 8; j++) {
            int n = 8 * j + 2 * qc;
            bzc[j][0] = g_c[n]; bzc[j][1] = g_c[n + 1];
        }
        #pragma unroll
        for (int j = 0; j < 4; j++) {
            int n = 8 * j + 2 * qc;
            bhc[j][0] = g_c[64 + n]; bhc[j][1] = g_c[64 + n + 1];
        }

        int n0 = min(base + qr,     N - 1);
        int n1 = min(base + qr + 8, N - 1);
        const unsigned* A0 = (const unsigned*)(g_aggh + (size_t)n0 * FT) + qc;
        const unsigned* A1 = (const unsigned*)(g_aggh + (size_t)n1 * FT) + qc;

        float H[4][4], acc[4][4];
        #pragma unroll
        for (int j = 0; j < 4; j++)
            #pragma unroll
            for (int i = 0; i < 4; i++) { H[j][i] = 0.0f; acc[j][i] = 0.0f; }

        #pragma unroll 1
        for (int t = 0; t < TT; t++) {
            float p = sp[t];
            unsigned af[4];
            af[0] = A0[t * 8];     af[1] = A1[t * 8];
            af[2] = A0[t * 8 + 4]; af[3] = A1[t * 8 + 4];

            unsigned hA1[4] = { h2pack(H[0][0], H[0][1]), h2pack(H[0][2], H[0][3]),
                                h2pack(H[1][0], H[1][1]), h2pack(H[1][2], H[1][3]) };
            unsigned hA2[4] = { h2pack(H[2][0], H[2][1]), h2pack(H[2][2], H[2][3]),
                                h2pack(H[3][0], H[3][1]), h2pack(H[3][2], H[3][3]) };

            // ---- z,r GEMM ----
            float Czr[8][4];
            #pragma unroll
            for (int j = 0; j < 8; j++) {
                Czr[j][0] = bzc[j][0]; Czr[j][1] = bzc[j][1];
                Czr[j][2] = bzc[j][0]; Czr[j][3] = bzc[j][1];
            }
            #pragma unroll
            for (int j = 0; j < 8; j++) {
                mma16816(Czr[j], af,  bzr[0][j]);
                mma16816(Czr[j], hA1, bzr[1][j]);
                mma16816(Czr[j], hA2, bzr[2][j]);
            }
            float Z[4][4], R[4][4];
            #pragma unroll
            for (int j = 0; j < 4; j++)
                #pragma unroll
                for (int i = 0; i < 4; i++) {
                    Z[j][i] = sigf(Czr[j][i]);
                    R[j][i] = sigf(Czr[4 + j][i]) * H[j][i];
                }

            // ---- candidate GEMM ----
            unsigned rA1[4] = { h2pack(R[0][0], R[0][1]), h2pack(R[0][2], R[0][3]),
                                h2pack(R[1][0], R[1][1]), h2pack(R[1][2], R[1][3]) };
            unsigned rA2[4] = { h2pack(R[2][0], R[2][1]), h2pack(R[2][2], R[2][3]),
                                h2pack(R[3][0], R[3][1]), h2pack(R[3][2], R[3][3]) };
            float Ch[4][4];
            #pragma unroll
            for (int j = 0; j < 4; j++) {
                Ch[j][0] = bhc[j][0]; Ch[j][1] = bhc[j][1];
                Ch[j][2] = bhc[j][0]; Ch[j][3] = bhc[j][1];
            }
            #pragma unroll
            for (int j = 0; j < 4; j++) {
                mma16816(Ch[j], af,  bh[0][j]);
                mma16816(Ch[j], rA1, bh[1][j]);
                mma16816(Ch[j], rA2, bh[2][j]);
            }
            // ---- state update ----
            #pragma unroll
            for (int j = 0; j < 4; j++)
                #pragma unroll
                for (int i = 0; i < 4; i++) {
                    float ht = tanhfast(Ch[j][i]);
                    float z = Z[j][i];
                    H[j][i] = z * H[j][i] + (1.0f - z) * ht;
                    acc[j][i] = fmaf(p, H[j][i], acc[j][i]);
                }
        }

        // ---- relu + reduce ----
        bool v0 = (base + qr)     < N;
        bool v1 = (base + qr + 8) < N;
        #pragma unroll
        for (int j = 0; j < 4; j++) {
            float a0 = acc[j][0], a1 = acc[j][1], a2 = acc[j][2], a3 = acc[j][3];
            float s0 = (v0 ? fmaxf(a0, 0.0f) : 0.0f) + (v1 ? fmaxf(a2, 0.0f) : 0.0f);
            float s1 = (v0 ? fmaxf(a1, 0.0f) : 0.0f) + (v1 ? fmaxf(a3, 0.0f) : 0.0f);
            #pragma unroll
            for (int o = 4; o < 32; o <<= 1) {
                s0 += __shfl_xor_sync(0xffffffffu, s0, o);
                s1 += __shfl_xor_sync(0xffffffffu, s1, o);
            }
            if (qr == 0) {
                atomicAdd(&bsum[8 * j + 2 * qc],     s0);
                atomicAdd(&bsum[8 * j + 2 * qc + 1], s1);
            }
        }
    }
    __syncthreads();
    if (tid < HID) atomicAdd(&g_hsum[tid], bsum[tid]);
}

// Final readout; also re-zeros g_hsum for the next replay.
__global__ void k_final(const float* __restrict__ linW, const float* __restrict__ linb,
                        float* out, int N) {
    int j = threadIdx.x;   // 32 threads
    float invN = 1.0f / (float)N;
    float h = g_hsum[j];
    g_hsum[j] = 0.0f;
    float v = h * invN * linW[j];
    #pragma unroll
    for (int o = 16; o; o >>= 1) v += __shfl_xor_sync(0xffffffffu, v, o);
    if (j == 0) {
        float r = v + linb[0];
        out[0] = r > 0.0f ? r : 0.0f;
    }
}

// ---------------- launcher ----------------
extern "C" void kernel_launch(void* const* d_in, const int* in_sizes, int n_in,
                              void* d_out, int out_size) {
    const float* x    = (const float*)d_in[0];
    const int*   ei   = (const int*)  d_in[1];
    const float* att  = (const float*)d_in[2];
    const float* Wz   = (const float*)d_in[3];
    const float* bz   = (const float*)d_in[4];
    const float* Wr   = (const float*)d_in[5];
    const float* br   = (const float*)d_in[6];
    const float* Wh   = (const float*)d_in[7];
    const float* bh   = (const float*)d_in[8];
    const float* LzW  = (const float*)d_in[9];
    const float* Lzb  = (const float*)d_in[10];
    const float* LrW  = (const float*)d_in[11];
    const float* Lrb  = (const float*)d_in[12];
    const float* LhW  = (const float*)d_in[13];
    const float* Lhb  = (const float*)d_in[14];
    const float* linW = (const float*)d_in[15];
    const float* linb = (const float*)d_in[16];

    int N = in_sizes[0] / FT;
    int E = in_sizes[1] / 2;
    int NB = (N + SB - 1) / SB;
    int NW = (N + 15) / 16;             // gru warps (16 nodes each)
    int NF = (E + 3) / 4;               // fill threads (4 edges each)

    k_pre<<<(N + 3) / 4, 256>>>(x, ei, Wz, bz, Wr, br, Wh, bh,
                                LzW, Lzb, LrW, Lrb, LhW, Lhb, att, N, E);
    k_scan_a<<<NB, SB>>>(N);
    k_scan_b<<<1, 128>>>(NB, N, E);
    k_scan_c<<<NB, SB>>>(N);
    k_fill<<<(NF + 255) / 256, 256>>>(ei, E, N);
    k_gather<<<(N * 32 + 255) / 256, 256>>>(N);
    k_gru<<<(NW + 3) / 4, 128>>>(LzW, LrW, LhW, N);
    k_final<<<1, 32>>>(linW, linb, (float*)d_out, N);
}